// round 1
// baseline (speedup 1.0000x reference)
#include <cuda_runtime.h>
#include <math.h>

// ---------------------------------------------------------------------------
// InteractionBlock: fused fp32 baseline for GB300 (sm_103a)
//
// Pipeline:
//   K0  memset   : zero component sums + counts
//   k_prep       : node->component map + component counts (atomic)
//   k_h          : h = x @ lin1_w^T                      [N,128]
//   k_edge       : per-edge MLP (persistent, weights in smem) fused with
//                  gather h[src], scale by C, scatter-add DIRECTLY into the
//                  2000x128 component table (skips agg[N,128] entirely;
//                  valid because comp_member feeds a segment-sum).
//   k_final      : mean -> lin2 -> ssp -> lin  -> out    [2000,128]
// ---------------------------------------------------------------------------

#define HF 128
#define MAXN 50000
#define MAXC 2048
#define TE 64            // edges per tile in k_edge

__device__ float g_h[MAXN * HF];        // node projection
__device__ float g_comp[MAXC * HF];     // per-component message sums
__device__ float g_cnt[MAXC];           // per-component node counts
__device__ int   g_node2comp[MAXN];

__device__ __forceinline__ float sspf(float x) {
    // shifted softplus: log1p(exp(x)) - log(2), numerically stable
    float ax = fabsf(x);
    return fmaxf(x, 0.0f) + log1pf(__expf(-ax)) - 0.6931471805599453f;
}

// ---------------------------------------------------------------------------
__global__ void k_prep(const int* __restrict__ comp_member,
                       const int* __restrict__ comp_seg, int N) {
    int i = blockIdx.x * blockDim.x + threadIdx.x;
    if (i < N) {
        int node = comp_member[i];
        int c = comp_seg[i];
        g_node2comp[node] = c;
        atomicAdd(&g_cnt[c], 1.0f);
    }
}

// ---------------------------------------------------------------------------
// h = x @ lin1_w^T. Block: 256 threads, 64 nodes x 128 feats.
// dyn smem: wT[128][129] (transposed, conflict-free) + xs[64][128]
__global__ void __launch_bounds__(256) k_h(const float* __restrict__ x,
                                           const float* __restrict__ lin1_w,
                                           int N) {
    extern __shared__ float sm[];
    float* wT = sm;                 // 128*129
    float* xs = sm + 128 * 129;     // 64*128
    int tid = threadIdx.x;

    for (int idx = tid; idx < 128 * 128; idx += 256) {
        int f = idx >> 7, k = idx & 127;
        wT[k * 129 + f] = lin1_w[idx];          // coalesced read over k
    }
    int n0 = blockIdx.x * 64;
    for (int idx = tid; idx < 64 * 128; idx += 256) {
        int n = idx >> 7, k = idx & 127;
        int gn = n0 + n;
        xs[idx] = (gn < N) ? x[(size_t)gn * HF + k] : 0.0f;
    }
    __syncthreads();

    int f = tid & 127;
    int no = tid >> 7;              // 0..1
#pragma unroll
    for (int grp = 0; grp < 8; ++grp) {
        int e0 = no + 2 * (grp * 4);     // nodes e0, e0+2, e0+4, e0+6
        float a0 = 0.f, a1 = 0.f, a2 = 0.f, a3 = 0.f;
#pragma unroll 4
        for (int k4 = 0; k4 < 32; ++k4) {
            float w0 = wT[(4 * k4 + 0) * 129 + f];
            float w1 = wT[(4 * k4 + 1) * 129 + f];
            float w2 = wT[(4 * k4 + 2) * 129 + f];
            float w3 = wT[(4 * k4 + 3) * 129 + f];
            float4 v0 = *(const float4*)&xs[(e0    ) * 128 + 4 * k4];
            float4 v1 = *(const float4*)&xs[(e0 + 2) * 128 + 4 * k4];
            float4 v2 = *(const float4*)&xs[(e0 + 4) * 128 + 4 * k4];
            float4 v3 = *(const float4*)&xs[(e0 + 6) * 128 + 4 * k4];
            a0 = fmaf(v0.x, w0, a0); a0 = fmaf(v0.y, w1, a0);
            a0 = fmaf(v0.z, w2, a0); a0 = fmaf(v0.w, w3, a0);
            a1 = fmaf(v1.x, w0, a1); a1 = fmaf(v1.y, w1, a1);
            a1 = fmaf(v1.z, w2, a1); a1 = fmaf(v1.w, w3, a1);
            a2 = fmaf(v2.x, w0, a2); a2 = fmaf(v2.y, w1, a2);
            a2 = fmaf(v2.z, w2, a2); a2 = fmaf(v2.w, w3, a2);
            a3 = fmaf(v3.x, w0, a3); a3 = fmaf(v3.y, w1, a3);
            a3 = fmaf(v3.z, w2, a3); a3 = fmaf(v3.w, w3, a3);
        }
        int gn = n0 + e0;
        if (gn     < N) g_h[(size_t)(gn    ) * HF + f] = a0;
        if (gn + 2 < N) g_h[(size_t)(gn + 2) * HF + f] = a1;
        if (gn + 4 < N) g_h[(size_t)(gn + 4) * HF + f] = a2;
        if (gn + 6 < N) g_h[(size_t)(gn + 6) * HF + f] = a3;
    }
}

// ---------------------------------------------------------------------------
// Persistent fused edge kernel. 512 threads, weights resident in smem.
// smem floats: w1T 6400 | w2T 16384 | b1 128 | b2 128 | sa 3200 | hs 8192 |
//              sC 64 | sSrc 64 | sComp 64   => 34624 floats = 138496 B
__global__ void __launch_bounds__(512, 1) k_edge(
    const int* __restrict__ ei, const float* __restrict__ ew,
    const float* __restrict__ attr,
    const float* __restrict__ w1, const float* __restrict__ b1,
    const float* __restrict__ w2, const float* __restrict__ b2,
    int E) {
    extern __shared__ float sm[];
    float* w1T  = sm;                  // [50][128]  (g-major, f contiguous)
    float* w2T  = sm + 6400;           // [128][128] (k-major, f contiguous)
    float* b1s  = sm + 22784;
    float* b2s  = sm + 22912;
    float* sa   = sm + 23040;          // [TE][50]
    float* hs   = sm + 26240;          // [TE][128]
    float* sC   = sm + 34432;          // [TE]
    int*   sSrc = (int*)(sm + 34496);  // [TE]
    int*   sComp= (int*)(sm + 34560);  // [TE]

    int tid = threadIdx.x;
    // one-time weight staging (transposed in smem; conflicts here are one-shot)
    for (int idx = tid; idx < 6400; idx += 512) {
        int ff = idx / 50, g = idx % 50;
        w1T[g * 128 + ff] = w1[idx];
    }
    for (int idx = tid; idx < 16384; idx += 512) {
        int ff = idx >> 7, k = idx & 127;
        w2T[k * 128 + ff] = w2[idx];
    }
    if (tid < 128) { b1s[tid] = b1[tid]; b2s[tid] = b2[tid]; }
    __syncthreads();

    int f  = tid & 127;
    int eo = tid >> 7;                 // 0..3
    int numTiles = (E + TE - 1) / TE;

    for (int tile = blockIdx.x; tile < numTiles; tile += gridDim.x) {
        int ebase = tile * TE;
        // per-edge metadata
        if (tid < TE) {
            int e = ebase + tid;
            if (e < E) {
                int s = ei[e];
                int d = ei[E + e];
                sSrc[tid]  = s;
                sComp[tid] = g_node2comp[d];
                float w = ew[e];
                sC[tid] = 10.0f / (1e-10f + w * w) - 1.0f;
            } else {
                sSrc[tid] = 0; sComp[tid] = -1; sC[tid] = 0.0f;
            }
        }
        // edge_attr tile (coalesced)
        for (int idx = tid; idx < TE * 50; idx += 512) {
            int ge = ebase + idx / 50;
            sa[idx] = (ge < E) ? attr[(size_t)ebase * 50 + idx] : 0.0f;
        }
        __syncthreads();

        // ---- stage 1: hidden = ssp(attr @ w1^T + b1) ----
#pragma unroll
        for (int grp = 0; grp < 4; ++grp) {
            int e0 = eo + 16 * grp;    // edges e0, e0+4, e0+8, e0+12
            float a0 = b1s[f], a1 = b1s[f], a2 = b1s[f], a3 = b1s[f];
#pragma unroll 5
            for (int g2 = 0; g2 < 25; ++g2) {
                float u0 = w1T[(2 * g2    ) * 128 + f];
                float u1 = w1T[(2 * g2 + 1) * 128 + f];
                float2 x0 = *(const float2*)&sa[(e0     ) * 50 + 2 * g2];
                float2 x1 = *(const float2*)&sa[(e0 +  4) * 50 + 2 * g2];
                float2 x2 = *(const float2*)&sa[(e0 +  8) * 50 + 2 * g2];
                float2 x3 = *(const float2*)&sa[(e0 + 12) * 50 + 2 * g2];
                a0 = fmaf(x0.x, u0, a0); a0 = fmaf(x0.y, u1, a0);
                a1 = fmaf(x1.x, u0, a1); a1 = fmaf(x1.y, u1, a1);
                a2 = fmaf(x2.x, u0, a2); a2 = fmaf(x2.y, u1, a2);
                a3 = fmaf(x3.x, u0, a3); a3 = fmaf(x3.y, u1, a3);
            }
            hs[(e0     ) * 128 + f] = sspf(a0);
            hs[(e0 +  4) * 128 + f] = sspf(a1);
            hs[(e0 +  8) * 128 + f] = sspf(a2);
            hs[(e0 + 12) * 128 + f] = sspf(a3);
        }
        __syncthreads();

        // ---- stage 2: W = hidden @ w2^T + b2; fuse C, h[src], scatter ----
#pragma unroll
        for (int grp = 0; grp < 4; ++grp) {
            int e0 = eo + 16 * grp;
            float a0 = b2s[f], a1 = b2s[f], a2 = b2s[f], a3 = b2s[f];
#pragma unroll 4
            for (int k4 = 0; k4 < 32; ++k4) {
                float ww0 = w2T[(4 * k4 + 0) * 128 + f];
                float ww1 = w2T[(4 * k4 + 1) * 128 + f];
                float ww2 = w2T[(4 * k4 + 2) * 128 + f];
                float ww3 = w2T[(4 * k4 + 3) * 128 + f];
                float4 h0 = *(const float4*)&hs[(e0     ) * 128 + 4 * k4];
                float4 h1 = *(const float4*)&hs[(e0 +  4) * 128 + 4 * k4];
                float4 h2 = *(const float4*)&hs[(e0 +  8) * 128 + 4 * k4];
                float4 h3 = *(const float4*)&hs[(e0 + 12) * 128 + 4 * k4];
                a0 = fmaf(h0.x, ww0, a0); a0 = fmaf(h0.y, ww1, a0);
                a0 = fmaf(h0.z, ww2, a0); a0 = fmaf(h0.w, ww3, a0);
                a1 = fmaf(h1.x, ww0, a1); a1 = fmaf(h1.y, ww1, a1);
                a1 = fmaf(h1.z, ww2, a1); a1 = fmaf(h1.w, ww3, a1);
                a2 = fmaf(h2.x, ww0, a2); a2 = fmaf(h2.y, ww1, a2);
                a2 = fmaf(h2.z, ww2, a2); a2 = fmaf(h2.w, ww3, a2);
                a3 = fmaf(h3.x, ww0, a3); a3 = fmaf(h3.y, ww1, a3);
                a3 = fmaf(h3.z, ww2, a3); a3 = fmaf(h3.w, ww3, a3);
            }
            int c0 = sComp[e0], c1 = sComp[e0 + 4], c2 = sComp[e0 + 8], c3 = sComp[e0 + 12];
            if (c0 >= 0)
                atomicAdd(&g_comp[c0 * HF + f],
                          a0 * sC[e0] * g_h[(size_t)sSrc[e0] * HF + f]);
            if (c1 >= 0)
                atomicAdd(&g_comp[c1 * HF + f],
                          a1 * sC[e0 + 4] * g_h[(size_t)sSrc[e0 + 4] * HF + f]);
            if (c2 >= 0)
                atomicAdd(&g_comp[c2 * HF + f],
                          a2 * sC[e0 + 8] * g_h[(size_t)sSrc[e0 + 8] * HF + f]);
            if (c3 >= 0)
                atomicAdd(&g_comp[c3 * HF + f],
                          a3 * sC[e0 + 12] * g_h[(size_t)sSrc[e0 + 12] * HF + f]);
        }
        __syncthreads();
    }
}

// ---------------------------------------------------------------------------
// Tail: mean -> lin2 + b -> ssp -> lin + b -> out. 16 comps per block.
__global__ void __launch_bounds__(256) k_final(
    const float* __restrict__ lin2_w, const float* __restrict__ lin2_b,
    const float* __restrict__ lin_w,  const float* __restrict__ lin_b,
    float* __restrict__ out) {
    __shared__ float sin_[16 * 128];
    __shared__ float sy[16 * 128];
    __shared__ float swT[32 * 129];
    int tid = threadIdx.x;
    int c0 = blockIdx.x * 16;

    for (int idx = tid; idx < 2048; idx += 256) {
        int c = idx >> 7;
        float cnt = g_cnt[c0 + c];
        sin_[idx] = g_comp[(c0 + c) * HF + (idx & 127)] / fmaxf(cnt, 1.0f);
    }
    __syncthreads();

    int f  = tid & 127;
    int co = tid >> 7;                 // 0..1
    float acc[8];
#pragma unroll
    for (int j = 0; j < 8; ++j) acc[j] = lin2_b[f];
    for (int kb = 0; kb < 4; ++kb) {
        __syncthreads();
        for (int idx = tid; idx < 4096; idx += 256) {
            int f_ = idx >> 5, kk = idx & 31;
            swT[kk * 129 + f_] = lin2_w[f_ * 128 + kb * 32 + kk];
        }
        __syncthreads();
        for (int kk = 0; kk < 32; ++kk) {
            float wv = swT[kk * 129 + f];
#pragma unroll
            for (int j = 0; j < 8; ++j)
                acc[j] = fmaf(sin_[(co + 2 * j) * 128 + kb * 32 + kk], wv, acc[j]);
        }
    }
#pragma unroll
    for (int j = 0; j < 8; ++j)
        sy[(co + 2 * j) * 128 + f] = sspf(acc[j]);

    float acc2[8];
#pragma unroll
    for (int j = 0; j < 8; ++j) acc2[j] = lin_b[f];
    for (int kb = 0; kb < 4; ++kb) {
        __syncthreads();
        for (int idx = tid; idx < 4096; idx += 256) {
            int f_ = idx >> 5, kk = idx & 31;
            swT[kk * 129 + f_] = lin_w[f_ * 128 + kb * 32 + kk];
        }
        __syncthreads();
        for (int kk = 0; kk < 32; ++kk) {
            float wv = swT[kk * 129 + f];
#pragma unroll
            for (int j = 0; j < 8; ++j)
                acc2[j] = fmaf(sy[(co + 2 * j) * 128 + kb * 32 + kk], wv, acc2[j]);
        }
    }
#pragma unroll
    for (int j = 0; j < 8; ++j)
        out[(size_t)(c0 + co + 2 * j) * HF + f] = acc2[j];
}

// ---------------------------------------------------------------------------
extern "C" void kernel_launch(void* const* d_in, const int* in_sizes, int n_in,
                              void* d_out, int out_size) {
    const float* x        = (const float*)d_in[0];
    const int*   ei       = (const int*)  d_in[1];
    const float* ew       = (const float*)d_in[2];
    const float* attr     = (const float*)d_in[3];
    const int*   cmember  = (const int*)  d_in[4];
    const int*   cseg     = (const int*)  d_in[5];
    const float* mlp_w1   = (const float*)d_in[6];
    const float* mlp_b1   = (const float*)d_in[7];
    const float* mlp_w2   = (const float*)d_in[8];
    const float* mlp_b2   = (const float*)d_in[9];
    const float* lin1_w   = (const float*)d_in[10];
    const float* lin2_w   = (const float*)d_in[11];
    const float* lin2_b   = (const float*)d_in[12];
    const float* lin_w    = (const float*)d_in[13];
    const float* lin_b    = (const float*)d_in[14];
    float* out = (float*)d_out;

    int N = in_sizes[0] / HF;
    int E = in_sizes[2];
    int NC = out_size / HF;

    void *p_comp, *p_cnt;
    cudaGetSymbolAddress(&p_comp, g_comp);
    cudaGetSymbolAddress(&p_cnt, g_cnt);
    cudaMemsetAsync(p_comp, 0, (size_t)NC * HF * sizeof(float));
    cudaMemsetAsync(p_cnt, 0, (size_t)NC * sizeof(float));

    int sms = 148;
    int dev = 0;
    cudaGetDevice(&dev);
    cudaDeviceGetAttribute(&sms, cudaDevAttrMultiProcessorCount, dev);

    const int SMEM_H = (128 * 129 + 64 * 128) * 4;   // 98816
    const int SMEM_E = 34624 * 4;                    // 138496
    cudaFuncSetAttribute(k_h, cudaFuncAttributeMaxDynamicSharedMemorySize, SMEM_H);
    cudaFuncSetAttribute(k_edge, cudaFuncAttributeMaxDynamicSharedMemorySize, SMEM_E);

    k_prep<<<(N + 255) / 256, 256>>>(cmember, cseg, N);
    k_h<<<(N + 63) / 64, 256, SMEM_H>>>(x, lin1_w, N);
    k_edge<<<sms, 512, SMEM_E>>>(ei, ew, attr, mlp_w1, mlp_b1, mlp_w2, mlp_b2, E);
    k_final<<<NC / 16, 256>>>(lin2_w, lin2_b, lin_w, lin_b, out);
}

// round 2
// speedup vs baseline: 2.2070x; 2.2070x over previous
#include <cuda_runtime.h>
#include <math.h>

// ---------------------------------------------------------------------------
// InteractionBlock v2: FFMA2 (fma.rn.f32x2) + 2D register tiling edge kernel.
//   3x memset/zero | k_prep | k_h | k_edge (launch #6 for ncu) | k_final
// ---------------------------------------------------------------------------

#define HF   128
#define MAXN 50000
#define MAXC 2048
#define TE   128
#define NTHR 512

__device__ float g_h[MAXN * HF];
__device__ float g_comp[MAXC * HF];
__device__ float g_cnt[MAXC];
__device__ int   g_node2comp[MAXN];

typedef unsigned long long ull;

__device__ __forceinline__ ull fma2(ull a, ull b, ull c) {
    ull d;
    asm("fma.rn.f32x2 %0, %1, %2, %3;" : "=l"(d) : "l"(a), "l"(b), "l"(c));
    return d;
}
__device__ __forceinline__ ull splat2(float x) {
    unsigned u = __float_as_uint(x);
    ull d;
    asm("mov.b64 %0, {%1, %1};" : "=l"(d) : "r"(u));
    return d;
}
__device__ __forceinline__ float2 unpack2(ull v) {
    unsigned lo, hi;
    asm("mov.b64 {%0, %1}, %2;" : "=r"(lo), "=r"(hi) : "l"(v));
    return make_float2(__uint_as_float(lo), __uint_as_float(hi));
}

__device__ __forceinline__ float sspf(float x) {         // precise (tail kernel)
    float ax = fabsf(x);
    return fmaxf(x, 0.0f) + log1pf(__expf(-ax)) - 0.6931471805599453f;
}
__device__ __forceinline__ float sspf_fast(float x) {    // MUFU-based
    float ax = fabsf(x);
    return fmaxf(x, 0.0f) + __logf(1.0f + __expf(-ax)) - 0.6931471805599453f;
}

__device__ __forceinline__ void cpa8(unsigned s, const void* g) {
    asm volatile("cp.async.ca.shared.global [%0], [%1], 8;" :: "r"(s), "l"(g));
}
__device__ __forceinline__ void cpa4(unsigned s, const void* g) {
    asm volatile("cp.async.ca.shared.global [%0], [%1], 4;" :: "r"(s), "l"(g));
}
#define CP_COMMIT() asm volatile("cp.async.commit_group;" ::: "memory")
#define CP_WAIT0()  asm volatile("cp.async.wait_group 0;" ::: "memory")

// smem float offsets for k_edge
#define OFF_W1   0        // [52][128]
#define OFF_W2   6656     // [128][128]
#define OFF_B1   23040    // [128]
#define OFF_B2   23168    // [128]
#define OFF_SA   23296    // [2][128][52]
#define OFF_HS   36608    // [128][128]
#define OFF_SRC  52992    // int [2][128]
#define OFF_CMP  53248    // int [2][128]
#define OFF_CV   53504    // float [2][128]
#define SMF_TOT  53760    // floats -> 215040 bytes

// ---------------------------------------------------------------------------
__global__ void k_prep(const int* __restrict__ comp_member,
                       const int* __restrict__ comp_seg, int N) {
    int i = blockIdx.x * blockDim.x + threadIdx.x;
    if (i < N) {
        int node = comp_member[i];
        int c = comp_seg[i];
        g_node2comp[node] = c;
        atomicAdd(&g_cnt[c], 1.0f);
    }
}

// ---------------------------------------------------------------------------
// h = x @ lin1_w^T (unchanged from round 1 — ~2% of runtime)
__global__ void __launch_bounds__(256) k_h(const float* __restrict__ x,
                                           const float* __restrict__ lin1_w,
                                           int N) {
    extern __shared__ float sm[];
    float* wT = sm;                 // 128*129
    float* xs = sm + 128 * 129;     // 64*128
    int tid = threadIdx.x;

    for (int idx = tid; idx < 128 * 128; idx += 256) {
        int f = idx >> 7, k = idx & 127;
        wT[k * 129 + f] = lin1_w[idx];
    }
    int n0 = blockIdx.x * 64;
    for (int idx = tid; idx < 64 * 128; idx += 256) {
        int n = idx >> 7, k = idx & 127;
        int gn = n0 + n;
        xs[idx] = (gn < N) ? x[(size_t)gn * HF + k] : 0.0f;
    }
    __syncthreads();

    int f = tid & 127;
    int no = tid >> 7;
#pragma unroll
    for (int grp = 0; grp < 8; ++grp) {
        int e0 = no + 2 * (grp * 4);
        float a0 = 0.f, a1 = 0.f, a2 = 0.f, a3 = 0.f;
#pragma unroll 4
        for (int k4 = 0; k4 < 32; ++k4) {
            float w0 = wT[(4 * k4 + 0) * 129 + f];
            float w1 = wT[(4 * k4 + 1) * 129 + f];
            float w2 = wT[(4 * k4 + 2) * 129 + f];
            float w3 = wT[(4 * k4 + 3) * 129 + f];
            float4 v0 = *(const float4*)&xs[(e0    ) * 128 + 4 * k4];
            float4 v1 = *(const float4*)&xs[(e0 + 2) * 128 + 4 * k4];
            float4 v2 = *(const float4*)&xs[(e0 + 4) * 128 + 4 * k4];
            float4 v3 = *(const float4*)&xs[(e0 + 6) * 128 + 4 * k4];
            a0 = fmaf(v0.x, w0, a0); a0 = fmaf(v0.y, w1, a0);
            a0 = fmaf(v0.z, w2, a0); a0 = fmaf(v0.w, w3, a0);
            a1 = fmaf(v1.x, w0, a1); a1 = fmaf(v1.y, w1, a1);
            a1 = fmaf(v1.z, w2, a1); a1 = fmaf(v1.w, w3, a1);
            a2 = fmaf(v2.x, w0, a2); a2 = fmaf(v2.y, w1, a2);
            a2 = fmaf(v2.z, w2, a2); a2 = fmaf(v2.w, w3, a2);
            a3 = fmaf(v3.x, w0, a3); a3 = fmaf(v3.y, w1, a3);
            a3 = fmaf(v3.z, w2, a3); a3 = fmaf(v3.w, w3, a3);
        }
        int gn = n0 + e0;
        if (gn     < N) g_h[(size_t)(gn    ) * HF + f] = a0;
        if (gn + 2 < N) g_h[(size_t)(gn + 2) * HF + f] = a1;
        if (gn + 4 < N) g_h[(size_t)(gn + 4) * HF + f] = a2;
        if (gn + 6 < N) g_h[(size_t)(gn + 6) * HF + f] = a3;
    }
}

// ---------------------------------------------------------------------------
// Persistent fused edge kernel v2.
// Thread tile: 8 edges x 4 features via f32x2. TE=128 edges/tile.
// cp.async double-buffered attr + edge metadata.
__global__ void __launch_bounds__(NTHR, 1) k_edge(
    const int* __restrict__ ei, const float* __restrict__ ew,
    const float* __restrict__ attr,
    const float* __restrict__ w1, const float* __restrict__ b1,
    const float* __restrict__ w2, const float* __restrict__ b2,
    int E) {
    extern __shared__ float sm[];
    float* w1T   = sm + OFF_W1;
    float* w2T   = sm + OFF_W2;
    float* b1s   = sm + OFF_B1;
    float* b2s   = sm + OFF_B2;
    float* saAll = sm + OFF_SA;
    float* hs    = sm + OFF_HS;
    int*   sSrcB = (int*)(sm + OFF_SRC);
    int*   sCmpB = (int*)(sm + OFF_CMP);
    float* sCvB  = sm + OFF_CV;
    unsigned smem_u32 = (unsigned)__cvta_generic_to_shared(sm);

    int tid = threadIdx.x;

    // ---- one-time weight staging (transposed [k][f]) ----
    for (int idx = tid; idx < 52 * 128; idx += NTHR) {
        int k = idx >> 7, f = idx & 127;
        w1T[idx] = (k < 50) ? w1[f * 50 + k] : 0.0f;
    }
    for (int idx = tid; idx < 128 * 128; idx += NTHR) {
        int k = idx >> 7, f = idx & 127;
        w2T[idx] = w2[f * 128 + k];
    }
    if (tid < 128) { b1s[tid] = b1[tid]; b2s[tid] = b2[tid]; }
    // zero pad columns (k=50,51) of both attr buffers
    for (int idx = tid; idx < 2 * TE; idx += NTHR) {
        int b = idx >> 7, e = idx & 127;
        saAll[b * 6656 + e * 52 + 50] = 0.0f;
        saAll[b * 6656 + e * 52 + 51] = 0.0f;
    }

    int numTiles = (E + TE - 1) / TE;
    int tile = blockIdx.x;
    if (tile >= numTiles) return;

    const int c  = tid & 31;        // feature column: features 4c..4c+3
    const int r8 = (tid >> 5) * 8;  // first of 8 edges for this thread

    // ---- prologue: bring in first tile ----
    {
        int tbase = tile * TE;
        for (int idx = tid; idx < TE * 25; idx += NTHR) {
            int e = idx / 25, ch = idx - e * 25;
            int ge = tbase + e;
            if (ge < E)
                cpa8(smem_u32 + (OFF_SA + e * 52 + ch * 2) * 4,
                     attr + (size_t)ge * 50 + ch * 2);
        }
        if (tid < TE) {
            int ge = tbase + tid;
            if (ge < E) {
                cpa4(smem_u32 + (OFF_SRC + tid) * 4, ei + ge);
                cpa4(smem_u32 + (OFF_CMP + tid) * 4, ei + E + ge);
                cpa4(smem_u32 + (OFF_CV  + tid) * 4, ew + ge);
            }
        }
        CP_COMMIT(); CP_WAIT0();
        __syncthreads();
        if (tid < TE) {
            int ge = tbase + tid;
            int srcv = 0, compv = 0; float Cv = 0.0f;
            if (ge < E) {
                srcv = sSrcB[tid];
                int dstv = sCmpB[tid];
                compv = g_node2comp[dstv];
                float w = sCvB[tid];
                Cv = 10.0f / (1e-10f + w * w) - 1.0f;
            }
            sSrcB[tid] = srcv; sCmpB[tid] = compv; sCvB[tid] = Cv;
        }
        __syncthreads();
    }

    int buf = 0;
    for (; tile < numTiles; tile += gridDim.x) {
        int ntile = tile + gridDim.x;
        int nbuf = buf ^ 1;
        bool pf = (ntile < numTiles);

        // ---- prefetch next tile ----
        if (pf) {
            int tbase = ntile * TE;
            for (int idx = tid; idx < TE * 25; idx += NTHR) {
                int e = idx / 25, ch = idx - e * 25;
                int ge = tbase + e;
                if (ge < E)
                    cpa8(smem_u32 + (OFF_SA + nbuf * 6656 + e * 52 + ch * 2) * 4,
                         attr + (size_t)ge * 50 + ch * 2);
            }
            if (tid < TE) {
                int ge = tbase + tid;
                if (ge < E) {
                    cpa4(smem_u32 + (OFF_SRC + nbuf * 128 + tid) * 4, ei + ge);
                    cpa4(smem_u32 + (OFF_CMP + nbuf * 128 + tid) * 4, ei + E + ge);
                    cpa4(smem_u32 + (OFF_CV  + nbuf * 128 + tid) * 4, ew + ge);
                }
            }
        }
        CP_COMMIT();

        const float* saB = saAll + buf * 6656;
        ull accA[8], accB[8];

        // ---- stage 1: hidden = ssp(attr @ w1^T + b1) ----
        {
            ulonglong2 bi = *(const ulonglong2*)&b1s[4 * c];
#pragma unroll
            for (int i = 0; i < 8; ++i) { accA[i] = bi.x; accB[i] = bi.y; }
        }
#pragma unroll 4
        for (int k4 = 0; k4 < 13; ++k4) {
            ulonglong2 wk0 = *(const ulonglong2*)&w1T[(4 * k4 + 0) * 128 + 4 * c];
            ulonglong2 wk1 = *(const ulonglong2*)&w1T[(4 * k4 + 1) * 128 + 4 * c];
            ulonglong2 wk2 = *(const ulonglong2*)&w1T[(4 * k4 + 2) * 128 + 4 * c];
            ulonglong2 wk3 = *(const ulonglong2*)&w1T[(4 * k4 + 3) * 128 + 4 * c];
#pragma unroll
            for (int i = 0; i < 8; ++i) {
                float4 av = *(const float4*)&saB[(r8 + i) * 52 + 4 * k4];
                ull h;
                h = splat2(av.x); accA[i] = fma2(h, wk0.x, accA[i]); accB[i] = fma2(h, wk0.y, accB[i]);
                h = splat2(av.y); accA[i] = fma2(h, wk1.x, accA[i]); accB[i] = fma2(h, wk1.y, accB[i]);
                h = splat2(av.z); accA[i] = fma2(h, wk2.x, accA[i]); accB[i] = fma2(h, wk2.y, accB[i]);
                h = splat2(av.w); accA[i] = fma2(h, wk3.x, accA[i]); accB[i] = fma2(h, wk3.y, accB[i]);
            }
        }
#pragma unroll
        for (int i = 0; i < 8; ++i) {
            float2 a = unpack2(accA[i]);
            float2 b = unpack2(accB[i]);
            float4 o = make_float4(sspf_fast(a.x), sspf_fast(a.y),
                                   sspf_fast(b.x), sspf_fast(b.y));
            *(float4*)&hs[(r8 + i) * 128 + 4 * c] = o;
        }
        __syncthreads();

        // ---- stage 2: W = hidden @ w2^T + b2 ----
        {
            ulonglong2 bi = *(const ulonglong2*)&b2s[4 * c];
#pragma unroll
            for (int i = 0; i < 8; ++i) { accA[i] = bi.x; accB[i] = bi.y; }
        }
#pragma unroll 4
        for (int k4 = 0; k4 < 32; ++k4) {
            ulonglong2 wk0 = *(const ulonglong2*)&w2T[(4 * k4 + 0) * 128 + 4 * c];
            ulonglong2 wk1 = *(const ulonglong2*)&w2T[(4 * k4 + 1) * 128 + 4 * c];
            ulonglong2 wk2 = *(const ulonglong2*)&w2T[(4 * k4 + 2) * 128 + 4 * c];
            ulonglong2 wk3 = *(const ulonglong2*)&w2T[(4 * k4 + 3) * 128 + 4 * c];
#pragma unroll
            for (int i = 0; i < 8; ++i) {
                float4 hv = *(const float4*)&hs[(r8 + i) * 128 + 4 * k4];
                ull h;
                h = splat2(hv.x); accA[i] = fma2(h, wk0.x, accA[i]); accB[i] = fma2(h, wk0.y, accB[i]);
                h = splat2(hv.y); accA[i] = fma2(h, wk1.x, accA[i]); accB[i] = fma2(h, wk1.y, accB[i]);
                h = splat2(hv.z); accA[i] = fma2(h, wk2.x, accA[i]); accB[i] = fma2(h, wk2.y, accB[i]);
                h = splat2(hv.w); accA[i] = fma2(h, wk3.x, accA[i]); accB[i] = fma2(h, wk3.y, accB[i]);
            }
        }

        // ---- epilogue: msg = W * C * h[src]; scatter to component table ----
#pragma unroll
        for (int i = 0; i < 8; ++i) {
            int e = r8 + i;
            float C   = sCvB[buf * 128 + e];
            int srcn  = sSrcB[buf * 128 + e];
            int comp  = sCmpB[buf * 128 + e];
            float4 hv = *(const float4*)&g_h[(size_t)srcn * HF + 4 * c];
            float2 a = unpack2(accA[i]);
            float2 b = unpack2(accB[i]);
            float* dp = &g_comp[comp * HF + 4 * c];
            atomicAdd(dp + 0, a.x * C * hv.x);
            atomicAdd(dp + 1, a.y * C * hv.y);
            atomicAdd(dp + 2, b.x * C * hv.z);
            atomicAdd(dp + 3, b.y * C * hv.w);
        }

        CP_WAIT0();
        __syncthreads();

        // ---- transform next-tile metadata ----
        if (pf) {
            if (tid < TE) {
                int ge = ntile * TE + tid;
                int srcv = 0, compv = 0; float Cv = 0.0f;
                if (ge < E) {
                    srcv = sSrcB[nbuf * 128 + tid];
                    int dstv = sCmpB[nbuf * 128 + tid];
                    compv = g_node2comp[dstv];
                    float w = sCvB[nbuf * 128 + tid];
                    Cv = 10.0f / (1e-10f + w * w) - 1.0f;
                }
                sSrcB[nbuf * 128 + tid] = srcv;
                sCmpB[nbuf * 128 + tid] = compv;
                sCvB[nbuf * 128 + tid]  = Cv;
            }
            __syncthreads();
        }
        buf = nbuf;
    }
}

// ---------------------------------------------------------------------------
// Tail: mean -> lin2 -> ssp -> lin (unchanged from round 1)
__global__ void __launch_bounds__(256) k_final(
    const float* __restrict__ lin2_w, const float* __restrict__ lin2_b,
    const float* __restrict__ lin_w,  const float* __restrict__ lin_b,
    float* __restrict__ out) {
    __shared__ float sin_[16 * 128];
    __shared__ float sy[16 * 128];
    __shared__ float swT[32 * 129];
    int tid = threadIdx.x;
    int c0 = blockIdx.x * 16;

    for (int idx = tid; idx < 2048; idx += 256) {
        int c = idx >> 7;
        float cnt = g_cnt[c0 + c];
        sin_[idx] = g_comp[(c0 + c) * HF + (idx & 127)] / fmaxf(cnt, 1.0f);
    }
    __syncthreads();

    int f  = tid & 127;
    int co = tid >> 7;
    float acc[8];
#pragma unroll
    for (int j = 0; j < 8; ++j) acc[j] = lin2_b[f];
    for (int kb = 0; kb < 4; ++kb) {
        __syncthreads();
        for (int idx = tid; idx < 4096; idx += 256) {
            int f_ = idx >> 5, kk = idx & 31;
            swT[kk * 129 + f_] = lin2_w[f_ * 128 + kb * 32 + kk];
        }
        __syncthreads();
        for (int kk = 0; kk < 32; ++kk) {
            float wv = swT[kk * 129 + f];
#pragma unroll
            for (int j = 0; j < 8; ++j)
                acc[j] = fmaf(sin_[(co + 2 * j) * 128 + kb * 32 + kk], wv, acc[j]);
        }
    }
#pragma unroll
    for (int j = 0; j < 8; ++j)
        sy[(co + 2 * j) * 128 + f] = sspf(acc[j]);

    float acc2[8];
#pragma unroll
    for (int j = 0; j < 8; ++j) acc2[j] = lin_b[f];
    for (int kb = 0; kb < 4; ++kb) {
        __syncthreads();
        for (int idx = tid; idx < 4096; idx += 256) {
            int f_ = idx >> 5, kk = idx & 31;
            swT[kk * 129 + f_] = lin_w[f_ * 128 + kb * 32 + kk];
        }
        __syncthreads();
        for (int kk = 0; kk < 32; ++kk) {
            float wv = swT[kk * 129 + f];
#pragma unroll
            for (int j = 0; j < 8; ++j)
                acc2[j] = fmaf(sy[(co + 2 * j) * 128 + kb * 32 + kk], wv, acc2[j]);
        }
    }
#pragma unroll
    for (int j = 0; j < 8; ++j)
        out[(size_t)(c0 + co + 2 * j) * HF + f] = acc2[j];
}

// ---------------------------------------------------------------------------
extern "C" void kernel_launch(void* const* d_in, const int* in_sizes, int n_in,
                              void* d_out, int out_size) {
    const float* x        = (const float*)d_in[0];
    const int*   ei       = (const int*)  d_in[1];
    const float* ew       = (const float*)d_in[2];
    const float* attr     = (const float*)d_in[3];
    const int*   cmember  = (const int*)  d_in[4];
    const int*   cseg     = (const int*)  d_in[5];
    const float* mlp_w1   = (const float*)d_in[6];
    const float* mlp_b1   = (const float*)d_in[7];
    const float* mlp_w2   = (const float*)d_in[8];
    const float* mlp_b2   = (const float*)d_in[9];
    const float* lin1_w   = (const float*)d_in[10];
    const float* lin2_w   = (const float*)d_in[11];
    const float* lin2_b   = (const float*)d_in[12];
    const float* lin_w    = (const float*)d_in[13];
    const float* lin_b    = (const float*)d_in[14];
    float* out = (float*)d_out;

    int N = in_sizes[0] / HF;
    int E = in_sizes[2];
    int NC = out_size / HF;

    void *p_comp, *p_cnt;
    cudaGetSymbolAddress(&p_comp, g_comp);
    cudaGetSymbolAddress(&p_cnt, g_cnt);

    int sms = 148;
    int dev = 0;
    cudaGetDevice(&dev);
    cudaDeviceGetAttribute(&sms, cudaDevAttrMultiProcessorCount, dev);

    const int SMEM_H = (128 * 129 + 64 * 128) * 4;   // 98816
    const int SMEM_E = SMF_TOT * 4;                  // 215040
    cudaFuncSetAttribute(k_h, cudaFuncAttributeMaxDynamicSharedMemorySize, SMEM_H);
    cudaFuncSetAttribute(k_edge, cudaFuncAttributeMaxDynamicSharedMemorySize, SMEM_E);

    // 3 memsets + k_prep + k_h = 5 launches before k_edge (ncu -s 5 captures k_edge)
    size_t compBytes = (size_t)NC * HF * sizeof(float);
    size_t half = (compBytes / 2) & ~(size_t)255;
    cudaMemsetAsync(p_comp, 0, half);                                   // 1
    cudaMemsetAsync((char*)p_comp + half, 0, compBytes - half);         // 2
    cudaMemsetAsync(p_cnt, 0, (size_t)NC * sizeof(float));              // 3
    k_prep<<<(N + 255) / 256, 256>>>(cmember, cseg, N);                 // 4
    k_h<<<(N + 63) / 64, 256, SMEM_H>>>(x, lin1_w, N);                  // 5
    k_edge<<<sms, NTHR, SMEM_E>>>(ei, ew, attr, mlp_w1, mlp_b1,         // 6
                                  mlp_w2, mlp_b2, E);
    k_final<<<NC / 16, 256>>>(lin2_w, lin2_b, lin_w, lin_b, out);       // 7
}

// round 3
// speedup vs baseline: 3.4234x; 1.5512x over previous
#include <cuda_runtime.h>
#include <math.h>
#include <stdint.h>

// ---------------------------------------------------------------------------
// InteractionBlock v3: bf16x3 tensor-core edge MLP (mma.sync.m16n8k16)
// k_edge: persistent, 256 thr (8 warps), 128-edge tiles, double-buffered
// cp.async. Stage1 C-frags reinterpreted as Stage2 A-frags in registers.
// Epilogue: shfl-pair -> LDG.128 h[src] -> red.global.add.v2.f32 scatter.
// ---------------------------------------------------------------------------

#define HF   128
#define MAXN 50000
#define MAXC 2048
#define TE   128
#define NTHR 256

__device__ float g_h[MAXN * HF];
__device__ float g_comp[MAXC * HF];
__device__ float g_cnt[MAXC];
__device__ int   g_node2comp[MAXN];

typedef unsigned int uint32;
typedef unsigned long long ull;

// ---- smem byte offsets for k_edge ----
#define OFF_STG 0          // fp32 attr staging [2][128][52]        53248
#define OFF_AH  53248      // bf16 [128 e][72 k]  (stride 144B)     18432
#define OFF_AL  71680      //                                       18432
#define OFF_W1H 90112      // bf16 [128 n][72 k]                    18432
#define OFF_W1L 108544     //                                       18432
#define OFF_W2H 126976     // bf16 [128 n][136 k] (stride 272B)     34816
#define OFF_W2L 161792     //                                       34816
#define OFF_B1  196608     // float[128]
#define OFF_B2  197120
#define OFF_SRC 197632     // int  [2][128]
#define OFF_CMP 198656     // int  [2][128]
#define OFF_CV  199680     // float[2][128]
#define SMEM_E  200704

__device__ __forceinline__ float sspf(float x) {
    float ax = fabsf(x);
    return fmaxf(x, 0.0f) + log1pf(__expf(-ax)) - 0.6931471805599453f;
}
__device__ __forceinline__ float sspf_fast(float x) {
    float ax = fabsf(x);
    return fmaxf(x, 0.0f) + __logf(1.0f + __expf(-ax)) - 0.6931471805599453f;
}

// pack two floats to bf16x2 (lo = first elem, hi = second)
__device__ __forceinline__ uint32 packbf2(float lo, float hi) {
    uint32 r;
    asm("cvt.rn.bf16x2.f32 %0, %1, %2;" : "=r"(r) : "f"(hi), "f"(lo));
    return r;
}
// split (x0,x1) into bf16 hi-pair and lo-pair (x = hi + lo)
__device__ __forceinline__ void split2(float x0, float x1, uint32& h, uint32& l) {
    h = packbf2(x0, x1);
    float h0 = __uint_as_float(h << 16);
    float h1 = __uint_as_float(h & 0xffff0000u);
    l = packbf2(x0 - h0, x1 - h1);
}

__device__ __forceinline__ void ldmx4(uint32& r0, uint32& r1, uint32& r2, uint32& r3,
                                      uint32 saddr) {
    asm volatile("ldmatrix.sync.aligned.m8n8.x4.shared.b16 {%0,%1,%2,%3}, [%4];"
                 : "=r"(r0), "=r"(r1), "=r"(r2), "=r"(r3) : "r"(saddr));
}
__device__ __forceinline__ void mma16816(float& d0, float& d1, float& d2, float& d3,
                                         uint32 a0, uint32 a1, uint32 a2, uint32 a3,
                                         uint32 b0, uint32 b1) {
    asm volatile("mma.sync.aligned.m16n8k16.row.col.f32.bf16.bf16.f32 "
                 "{%0,%1,%2,%3},{%4,%5,%6,%7},{%8,%9},{%0,%1,%2,%3};"
                 : "+f"(d0), "+f"(d1), "+f"(d2), "+f"(d3)
                 : "r"(a0), "r"(a1), "r"(a2), "r"(a3), "r"(b0), "r"(b1));
}
__device__ __forceinline__ void redv2(float* p, float x, float y) {
    asm volatile("red.global.add.v2.f32 [%0], {%1,%2};"
                 :: "l"((ull)p), "f"(x), "f"(y) : "memory");
}

__device__ __forceinline__ void cpa8(unsigned s, const void* g) {
    asm volatile("cp.async.ca.shared.global [%0], [%1], 8;" :: "r"(s), "l"(g));
}
__device__ __forceinline__ void cpa4(unsigned s, const void* g) {
    asm volatile("cp.async.ca.shared.global [%0], [%1], 4;" :: "r"(s), "l"(g));
}
#define CP_COMMIT() asm volatile("cp.async.commit_group;" ::: "memory")
#define CP_WAIT0()  asm volatile("cp.async.wait_group 0;" ::: "memory")

// ---------------------------------------------------------------------------
__global__ void k_prep(const int* __restrict__ comp_member,
                       const int* __restrict__ comp_seg, int N) {
    int i = blockIdx.x * blockDim.x + threadIdx.x;
    if (i < N) {
        int node = comp_member[i];
        int c = comp_seg[i];
        g_node2comp[node] = c;
        atomicAdd(&g_cnt[c], 1.0f);
    }
}

// ---------------------------------------------------------------------------
// h = x @ lin1_w^T  (fp32, unchanged)
__global__ void __launch_bounds__(256) k_h(const float* __restrict__ x,
                                           const float* __restrict__ lin1_w,
                                           int N) {
    extern __shared__ float smf[];
    float* wT = smf;
    float* xs = smf + 128 * 129;
    int tid = threadIdx.x;

    for (int idx = tid; idx < 128 * 128; idx += 256) {
        int f = idx >> 7, k = idx & 127;
        wT[k * 129 + f] = lin1_w[idx];
    }
    int n0 = blockIdx.x * 64;
    for (int idx = tid; idx < 64 * 128; idx += 256) {
        int n = idx >> 7, k = idx & 127;
        int gn = n0 + n;
        xs[idx] = (gn < N) ? x[(size_t)gn * HF + k] : 0.0f;
    }
    __syncthreads();

    int f = tid & 127;
    int no = tid >> 7;
#pragma unroll
    for (int grp = 0; grp < 8; ++grp) {
        int e0 = no + 2 * (grp * 4);
        float a0 = 0.f, a1 = 0.f, a2 = 0.f, a3 = 0.f;
#pragma unroll 4
        for (int k4 = 0; k4 < 32; ++k4) {
            float w0 = wT[(4 * k4 + 0) * 129 + f];
            float w1 = wT[(4 * k4 + 1) * 129 + f];
            float w2 = wT[(4 * k4 + 2) * 129 + f];
            float w3 = wT[(4 * k4 + 3) * 129 + f];
            float4 v0 = *(const float4*)&xs[(e0    ) * 128 + 4 * k4];
            float4 v1 = *(const float4*)&xs[(e0 + 2) * 128 + 4 * k4];
            float4 v2 = *(const float4*)&xs[(e0 + 4) * 128 + 4 * k4];
            float4 v3 = *(const float4*)&xs[(e0 + 6) * 128 + 4 * k4];
            a0 = fmaf(v0.x, w0, a0); a0 = fmaf(v0.y, w1, a0);
            a0 = fmaf(v0.z, w2, a0); a0 = fmaf(v0.w, w3, a0);
            a1 = fmaf(v1.x, w0, a1); a1 = fmaf(v1.y, w1, a1);
            a1 = fmaf(v1.z, w2, a1); a1 = fmaf(v1.w, w3, a1);
            a2 = fmaf(v2.x, w0, a2); a2 = fmaf(v2.y, w1, a2);
            a2 = fmaf(v2.z, w2, a2); a2 = fmaf(v2.w, w3, a2);
            a3 = fmaf(v3.x, w0, a3); a3 = fmaf(v3.y, w1, a3);
            a3 = fmaf(v3.z, w2, a3); a3 = fmaf(v3.w, w3, a3);
        }
        int gn = n0 + e0;
        if (gn     < N) g_h[(size_t)(gn    ) * HF + f] = a0;
        if (gn + 2 < N) g_h[(size_t)(gn + 2) * HF + f] = a1;
        if (gn + 4 < N) g_h[(size_t)(gn + 4) * HF + f] = a2;
        if (gn + 6 < N) g_h[(size_t)(gn + 6) * HF + f] = a3;
    }
}

// ---------------------------------------------------------------------------
__global__ void __launch_bounds__(NTHR, 1) k_edge(
    const int* __restrict__ ei, const float* __restrict__ ew,
    const float* __restrict__ attr,
    const float* __restrict__ w1, const float* __restrict__ b1,
    const float* __restrict__ w2, const float* __restrict__ b2,
    int E) {
    extern __shared__ char sm[];
    float* stg   = (float*)(sm + OFF_STG);
    float* b1s   = (float*)(sm + OFF_B1);
    float* b2s   = (float*)(sm + OFF_B2);
    int*   sSrc  = (int*)  (sm + OFF_SRC);
    int*   sCmp  = (int*)  (sm + OFF_CMP);
    float* sCv   = (float*)(sm + OFF_CV);
    uint32 sbase = (uint32)__cvta_generic_to_shared(sm);

    const int tid = threadIdx.x;
    const int w   = tid >> 5;
    const int l   = tid & 31;
    const int g   = l >> 2;
    const int q   = l & 3;

    // ---- one-time weight staging: [n][k]-major bf16 hi/lo ----
    for (int idx = tid; idx < 128 * 36; idx += NTHR) {       // w1: k padded 50->72
        int n = idx / 36, kp = idx % 36;
        int k = 2 * kp;
        float v0 = (k     < 50) ? w1[n * 50 + k]     : 0.0f;
        float v1 = (k + 1 < 50) ? w1[n * 50 + k + 1] : 0.0f;
        uint32 h, lo;
        split2(v0, v1, h, lo);
        *(uint32*)(sm + OFF_W1H + n * 144 + kp * 4) = h;
        *(uint32*)(sm + OFF_W1L + n * 144 + kp * 4) = lo;
    }
    for (int idx = tid; idx < 128 * 68; idx += NTHR) {       // w2: k padded 128->136
        int n = idx / 68, kp = idx % 68;
        int k = 2 * kp;
        float v0 = (k < 128) ? w2[n * 128 + k]     : 0.0f;
        float v1 = (k < 128) ? w2[n * 128 + k + 1] : 0.0f;
        uint32 h, lo;
        split2(v0, v1, h, lo);
        *(uint32*)(sm + OFF_W2H + n * 272 + kp * 4) = h;
        *(uint32*)(sm + OFF_W2L + n * 272 + kp * 4) = lo;
    }
    if (tid < 128) { b1s[tid] = b1[tid]; b2s[tid] = b2[tid]; }

    const int numTiles = (E + TE - 1) / TE;
    int tile = blockIdx.x;
    if (tile >= numTiles) return;

    // ---- prologue prefetch of first tile (buf 0) ----
    {
        int tbase = tile * TE;
        for (int i = tid; i < TE * 25; i += NTHR) {
            int e = i / 25, ch = i - e * 25;
            int ge = tbase + e;
            if (ge < E)
                cpa8(sbase + OFF_STG + e * 208 + ch * 8,
                     attr + (size_t)ge * 50 + ch * 2);
        }
        if (tid < TE) {
            int ge = tbase + tid;
            if (ge < E) {
                cpa4(sbase + OFF_SRC + tid * 4, ei + ge);
                cpa4(sbase + OFF_CMP + tid * 4, ei + E + ge);
                cpa4(sbase + OFF_CV  + tid * 4, ew + ge);
            }
        }
        CP_COMMIT();
    }

    int buf = 0;
    for (; tile < numTiles; tile += gridDim.x) {
        int ntile = tile + gridDim.x;
        CP_WAIT0();
        __syncthreads();   // staged data ready; prev tile's smem reads done

        int ebase = tile * TE;
        // ---- transform metadata in place ----
        if (tid < TE) {
            int ge = ebase + tid;
            int srcv = 0, compv = 0;
            float Cv = 0.0f;
            if (ge < E) {
                srcv = sSrc[buf * 128 + tid];
                compv = g_node2comp[sCmp[buf * 128 + tid]];
                float wv = sCv[buf * 128 + tid];
                Cv = 10.0f / (1e-10f + wv * wv) - 1.0f;
            }
            sSrc[buf * 128 + tid] = srcv;
            sCmp[buf * 128 + tid] = compv;
            sCv [buf * 128 + tid] = Cv;
        }
        // ---- convert attr fp32 -> bf16 hi/lo (K padded to 64) ----
        {
            const float* sb = stg + buf * (128 * 52);
            for (int i = tid; i < 128 * 32; i += NTHR) {
                int row = i >> 5, kp = i & 31;
                int k = 2 * kp;
                float v0 = 0.f, v1 = 0.f;
                if (ebase + row < E && k < 50) {
                    v0 = sb[row * 52 + k];
                    v1 = (k + 1 < 50) ? sb[row * 52 + k + 1] : 0.0f;
                }
                uint32 h, lo;
                split2(v0, v1, h, lo);
                *(uint32*)(sm + OFF_AH + row * 144 + kp * 4) = h;
                *(uint32*)(sm + OFF_AL + row * 144 + kp * 4) = lo;
            }
        }
        // ---- prefetch next tile ----
        if (ntile < numTiles) {
            int tbase = ntile * TE;
            int nb = buf ^ 1;
            for (int i = tid; i < TE * 25; i += NTHR) {
                int e = i / 25, ch = i - e * 25;
                int ge = tbase + e;
                if (ge < E)
                    cpa8(sbase + OFF_STG + nb * (128 * 208) + e * 208 + ch * 8,
                         attr + (size_t)ge * 50 + ch * 2);
            }
            if (tid < TE) {
                int ge = tbase + tid;
                if (ge < E) {
                    cpa4(sbase + OFF_SRC + (nb * 128 + tid) * 4, ei + ge);
                    cpa4(sbase + OFF_CMP + (nb * 128 + tid) * 4, ei + E + ge);
                    cpa4(sbase + OFF_CV  + (nb * 128 + tid) * 4, ew + ge);
                }
            }
        }
        CP_COMMIT();
        __syncthreads();   // ah/al + meta visible

        // ---- load all stage-1 A fragments (hi & lo) ----
        uint32 ahf[4][4], alf[4][4];
        {
            uint32 arow = sbase + OFF_AH + (16 * w + (l & 15)) * 144 + ((l >> 4) * 16);
            uint32 lrow = arow + (OFF_AL - OFF_AH);
#pragma unroll
            for (int t = 0; t < 4; ++t) {
                ldmx4(ahf[t][0], ahf[t][1], ahf[t][2], ahf[t][3], arow + t * 32);
                ldmx4(alf[t][0], alf[t][1], alf[t][2], alf[t][3], lrow + t * 32);
            }
        }

        // per-lane edge metadata (row fixed across n-tiles)
        const int rowe = g + ((q & 1) << 3);
        const int eIdx = 16 * w + rowe;
        const float Cv = sCv[buf * 128 + eIdx];
        const int  srcn = sSrc[buf * 128 + eIdx];
        const int  comp = sCmp[buf * 128 + eIdx];

        // ---- stage-2 accumulators init with bias b2 ----
        float acc2[16][4];
#pragma unroll
        for (int nt = 0; nt < 16; ++nt) {
            float2 bb = *(const float2*)&b2s[8 * nt + 2 * q];
            acc2[nt][0] = bb.x; acc2[nt][1] = bb.y;
            acc2[nt][2] = bb.x; acc2[nt][3] = bb.y;
        }

        // ---- main: for each stage-2 k-tile j, compute hidden cols 16j..16j+15
        //      (stage-1 n-tiles 2j,2j+1), ssp, split, then 16 stage-2 MMAs ----
        for (int j = 0; j < 8; ++j) {
            float a1[2][4];
#pragma unroll
            for (int p = 0; p < 2; ++p) {
                float2 bb = *(const float2*)&b1s[16 * j + 8 * p + 2 * q];
                a1[p][0] = bb.x; a1[p][1] = bb.y;
                a1[p][2] = bb.x; a1[p][3] = bb.y;
            }
#pragma unroll
            for (int t = 0; t < 4; ++t) {
#pragma unroll
                for (int p = 0; p < 2; ++p) {
                    const char* wb = sm + (16 * j + 8 * p + g) * 144 + (16 * t + 2 * q) * 2;
                    uint32 bh0 = *(const uint32*)(wb + OFF_W1H);
                    uint32 bh1 = *(const uint32*)(wb + OFF_W1H + 16);
                    uint32 bl0 = *(const uint32*)(wb + OFF_W1L);
                    uint32 bl1 = *(const uint32*)(wb + OFF_W1L + 16);
                    mma16816(a1[p][0], a1[p][1], a1[p][2], a1[p][3],
                             ahf[t][0], ahf[t][1], ahf[t][2], ahf[t][3], bh0, bh1);
                    mma16816(a1[p][0], a1[p][1], a1[p][2], a1[p][3],
                             ahf[t][0], ahf[t][1], ahf[t][2], ahf[t][3], bl0, bl1);
                    mma16816(a1[p][0], a1[p][1], a1[p][2], a1[p][3],
                             alf[t][0], alf[t][1], alf[t][2], alf[t][3], bh0, bh1);
                }
            }
            // ssp + split -> stage-2 A fragments for k-tile j
            uint32 ua[4], la[4];
            split2(sspf_fast(a1[0][0]), sspf_fast(a1[0][1]), ua[0], la[0]);
            split2(sspf_fast(a1[0][2]), sspf_fast(a1[0][3]), ua[1], la[1]);
            split2(sspf_fast(a1[1][0]), sspf_fast(a1[1][1]), ua[2], la[2]);
            split2(sspf_fast(a1[1][2]), sspf_fast(a1[1][3]), ua[3], la[3]);

#pragma unroll
            for (int nt = 0; nt < 16; ++nt) {
                const char* wb = sm + (8 * nt + g) * 272 + (16 * j + 2 * q) * 2;
                uint32 bh0 = *(const uint32*)(wb + OFF_W2H);
                uint32 bh1 = *(const uint32*)(wb + OFF_W2H + 16);
                uint32 bl0 = *(const uint32*)(wb + OFF_W2L);
                uint32 bl1 = *(const uint32*)(wb + OFF_W2L + 16);
                mma16816(acc2[nt][0], acc2[nt][1], acc2[nt][2], acc2[nt][3],
                         ua[0], ua[1], ua[2], ua[3], bh0, bh1);
                mma16816(acc2[nt][0], acc2[nt][1], acc2[nt][2], acc2[nt][3],
                         ua[0], ua[1], ua[2], ua[3], bl0, bl1);
                mma16816(acc2[nt][0], acc2[nt][1], acc2[nt][2], acc2[nt][3],
                         la[0], la[1], la[2], la[3], bh0, bh1);
            }
        }

        // ---- epilogue: shuffle to row-major float4, scale, gather h, scatter ----
        {
            const float4* hrow = (const float4*)&g_h[(size_t)srcn * HF];
            float* crow = &g_comp[comp * HF];
            const bool doit = (Cv != 0.0f);
            const int podd = q & 1;
            const int p4 = (q >> 1) << 2;
#pragma unroll
            for (int nt = 0; nt < 16; ++nt) {
                float d0 = acc2[nt][0], d1 = acc2[nt][1];
                float d2 = acc2[nt][2], d3 = acc2[nt][3];
                ull send;
                if (podd) { asm("mov.b64 %0,{%1,%2};" : "=l"(send) : "f"(d0), "f"(d1)); }
                else      { asm("mov.b64 %0,{%1,%2};" : "=l"(send) : "f"(d2), "f"(d3)); }
                ull rcv = __shfl_xor_sync(0xffffffffu, send, 1);
                float rx, ry;
                asm("mov.b64 {%0,%1},%2;" : "=f"(rx), "=f"(ry) : "l"(rcv));
                float v0, v1, v2, v3;
                if (podd) { v0 = rx; v1 = ry; v2 = d2; v3 = d3; }
                else      { v0 = d0; v1 = d1; v2 = rx; v3 = ry; }
                int col0 = 8 * nt + p4;
                if (doit) {
                    float4 h4 = hrow[col0 >> 2];
                    v0 *= Cv * h4.x; v1 *= Cv * h4.y;
                    v2 *= Cv * h4.z; v3 *= Cv * h4.w;
                    redv2(crow + col0,     v0, v1);
                    redv2(crow + col0 + 2, v2, v3);
                }
            }
        }
        buf ^= 1;
    }
}

// ---------------------------------------------------------------------------
// Tail: mean -> lin2 -> ssp -> lin (unchanged)
__global__ void __launch_bounds__(256) k_final(
    const float* __restrict__ lin2_w, const float* __restrict__ lin2_b,
    const float* __restrict__ lin_w,  const float* __restrict__ lin_b,
    float* __restrict__ out) {
    __shared__ float sin_[16 * 128];
    __shared__ float sy[16 * 128];
    __shared__ float swT[32 * 129];
    int tid = threadIdx.x;
    int c0 = blockIdx.x * 16;

    for (int idx = tid; idx < 2048; idx += 256) {
        int c = idx >> 7;
        float cnt = g_cnt[c0 + c];
        sin_[idx] = g_comp[(c0 + c) * HF + (idx & 127)] / fmaxf(cnt, 1.0f);
    }
    __syncthreads();

    int f  = tid & 127;
    int co = tid >> 7;
    float acc[8];
#pragma unroll
    for (int j = 0; j < 8; ++j) acc[j] = lin2_b[f];
    for (int kb = 0; kb < 4; ++kb) {
        __syncthreads();
        for (int idx = tid; idx < 4096; idx += 256) {
            int f_ = idx >> 5, kk = idx & 31;
            swT[kk * 129 + f_] = lin2_w[f_ * 128 + kb * 32 + kk];
        }
        __syncthreads();
        for (int kk = 0; kk < 32; ++kk) {
            float wv = swT[kk * 129 + f];
#pragma unroll
            for (int j = 0; j < 8; ++j)
                acc[j] = fmaf(sin_[(co + 2 * j) * 128 + kb * 32 + kk], wv, acc[j]);
        }
    }
#pragma unroll
    for (int j = 0; j < 8; ++j)
        sy[(co + 2 * j) * 128 + f] = sspf(acc[j]);

    float acc2[8];
#pragma unroll
    for (int j = 0; j < 8; ++j) acc2[j] = lin_b[f];
    for (int kb = 0; kb < 4; ++kb) {
        __syncthreads();
        for (int idx = tid; idx < 4096; idx += 256) {
            int f_ = idx >> 5, kk = idx & 31;
            swT[kk * 129 + f_] = lin_w[f_ * 128 + kb * 32 + kk];
        }
        __syncthreads();
        for (int kk = 0; kk < 32; ++kk) {
            float wv = swT[kk * 129 + f];
#pragma unroll
            for (int j = 0; j < 8; ++j)
                acc2[j] = fmaf(sy[(co + 2 * j) * 128 + kb * 32 + kk], wv, acc2[j]);
        }
    }
#pragma unroll
    for (int j = 0; j < 8; ++j)
        out[(size_t)(c0 + co + 2 * j) * HF + f] = acc2[j];
}

// ---------------------------------------------------------------------------
extern "C" void kernel_launch(void* const* d_in, const int* in_sizes, int n_in,
                              void* d_out, int out_size) {
    const float* x        = (const float*)d_in[0];
    const int*   ei       = (const int*)  d_in[1];
    const float* ew       = (const float*)d_in[2];
    const float* attr     = (const float*)d_in[3];
    const int*   cmember  = (const int*)  d_in[4];
    const int*   cseg     = (const int*)  d_in[5];
    const float* mlp_w1   = (const float*)d_in[6];
    const float* mlp_b1   = (const float*)d_in[7];
    const float* mlp_w2   = (const float*)d_in[8];
    const float* mlp_b2   = (const float*)d_in[9];
    const float* lin1_w   = (const float*)d_in[10];
    const float* lin2_w   = (const float*)d_in[11];
    const float* lin2_b   = (const float*)d_in[12];
    const float* lin_w    = (const float*)d_in[13];
    const float* lin_b    = (const float*)d_in[14];
    float* out = (float*)d_out;

    int N = in_sizes[0] / HF;
    int E = in_sizes[2];
    int NC = out_size / HF;

    void *p_comp, *p_cnt;
    cudaGetSymbolAddress(&p_comp, g_comp);
    cudaGetSymbolAddress(&p_cnt, g_cnt);
    cudaMemsetAsync(p_comp, 0, (size_t)NC * HF * sizeof(float));
    cudaMemsetAsync(p_cnt, 0, (size_t)NC * sizeof(float));

    int sms = 148;
    int dev = 0;
    cudaGetDevice(&dev);
    cudaDeviceGetAttribute(&sms, cudaDevAttrMultiProcessorCount, dev);

    const int SMEM_H = (128 * 129 + 64 * 128) * 4;
    cudaFuncSetAttribute(k_h, cudaFuncAttributeMaxDynamicSharedMemorySize, SMEM_H);
    cudaFuncSetAttribute(k_edge, cudaFuncAttributeMaxDynamicSharedMemorySize, SMEM_E);

    int numTiles = (E + TE - 1) / TE;
    int grid = sms < numTiles ? sms : numTiles;

    k_prep<<<(N + 255) / 256, 256>>>(cmember, cseg, N);
    k_h<<<(N + 63) / 64, 256, SMEM_H>>>(x, lin1_w, N);
    k_edge<<<grid, NTHR, SMEM_E>>>(ei, ew, attr, mlp_w1, mlp_b1,
                                   mlp_w2, mlp_b2, E);
    k_final<<<NC / 16, 256>>>(lin2_w, lin2_b, lin_w, lin_b, out);
}

// round 5
// speedup vs baseline: 3.7750x; 1.1027x over previous
#include <cuda_runtime.h>
#include <cuda_fp16.h>
#include <math.h>
#include <stdint.h>

// ---------------------------------------------------------------------------
// InteractionBlock v5: fp16x2 tensor-core edge MLP (mma.sync.m16n8k16.f16)
// Weights split hi/lo fp16 (exact, one-time); activations rounded once.
// 2 HMMA per site (vs 3 in v3's bf16x3). tcgen05 unavailable (.target sm_103).
// ---------------------------------------------------------------------------

#define HF   128
#define MAXN 50000
#define MAXC 2048
#define TE   128
#define NTHR 256

__device__ float g_h[MAXN * HF];
__device__ float g_comp[MAXC * HF];
__device__ float g_cnt[MAXC];
__device__ int   g_node2comp[MAXN];

typedef unsigned int uint32;
typedef unsigned long long ull;

// ---- smem byte offsets for k_edge ----
#define OFF_STG 0          // fp32 attr staging [2][128][52]      53248
#define OFF_AH  53248      // fp16 [128 e][72 k] (stride 144B)    18432
#define OFF_W1H 71680      // fp16 [128 n][72 k]                  18432
#define OFF_W1L 90112      //                                     18432
#define OFF_W2H 108544     // fp16 [128 n][136 k] (stride 272B)   34816
#define OFF_W2L 143360     //                                     34816
#define OFF_B1  178176     // float[128]
#define OFF_B2  178688
#define OFF_SRC 179200     // int  [2][128]
#define OFF_CMP 180224     // int  [2][128]
#define OFF_CV  181248     // float[2][128]
#define SMEM_E  182272

__device__ __forceinline__ float sspf(float x) {
    float ax = fabsf(x);
    return fmaxf(x, 0.0f) + log1pf(__expf(-ax)) - 0.6931471805599453f;
}
__device__ __forceinline__ float sspf_fast(float x) {
    float ax = fabsf(x);
    return fmaxf(x, 0.0f) + __logf(1.0f + __expf(-ax)) - 0.6931471805599453f;
}

// pack two floats into fp16x2 (lo = x0, hi = x1)
__device__ __forceinline__ uint32 packh2(float x0, float x1) {
    __half2 hh = __floats2half2_rn(x0, x1);
    return *reinterpret_cast<uint32*>(&hh);
}
// exact hi/lo fp16 split of a float pair (x = hi + lo to ~2^-22)
__device__ __forceinline__ void split2h(float x0, float x1, uint32& h, uint32& l) {
    __half2 hh = __floats2half2_rn(x0, x1);
    float2 b = __half22float2(hh);
    __half2 ll = __floats2half2_rn(x0 - b.x, x1 - b.y);
    h = *reinterpret_cast<uint32*>(&hh);
    l = *reinterpret_cast<uint32*>(&ll);
}

__device__ __forceinline__ void ldmx4(uint32& r0, uint32& r1, uint32& r2, uint32& r3,
                                      uint32 saddr) {
    asm volatile("ldmatrix.sync.aligned.m8n8.x4.shared.b16 {%0,%1,%2,%3}, [%4];"
                 : "=r"(r0), "=r"(r1), "=r"(r2), "=r"(r3) : "r"(saddr));
}
__device__ __forceinline__ void mma16816(float& d0, float& d1, float& d2, float& d3,
                                         uint32 a0, uint32 a1, uint32 a2, uint32 a3,
                                         uint32 b0, uint32 b1) {
    asm volatile("mma.sync.aligned.m16n8k16.row.col.f32.f16.f16.f32 "
                 "{%0,%1,%2,%3},{%4,%5,%6,%7},{%8,%9},{%0,%1,%2,%3};"
                 : "+f"(d0), "+f"(d1), "+f"(d2), "+f"(d3)
                 : "r"(a0), "r"(a1), "r"(a2), "r"(a3), "r"(b0), "r"(b1));
}
__device__ __forceinline__ void redv2(float* p, float x, float y) {
    asm volatile("red.global.add.v2.f32 [%0], {%1,%2};"
                 :: "l"((ull)p), "f"(x), "f"(y) : "memory");
}
__device__ __forceinline__ void cpa8(unsigned s, const void* g) {
    asm volatile("cp.async.ca.shared.global [%0], [%1], 8;" :: "r"(s), "l"(g));
}
__device__ __forceinline__ void cpa4(unsigned s, const void* g) {
    asm volatile("cp.async.ca.shared.global [%0], [%1], 4;" :: "r"(s), "l"(g));
}
#define CP_COMMIT() asm volatile("cp.async.commit_group;" ::: "memory")
#define CP_WAIT0()  asm volatile("cp.async.wait_group 0;" ::: "memory")

// ---------------------------------------------------------------------------
__global__ void k_prep(const int* __restrict__ comp_member,
                       const int* __restrict__ comp_seg, int N) {
    int i = blockIdx.x * blockDim.x + threadIdx.x;
    if (i < N) {
        int node = comp_member[i];
        int c = comp_seg[i];
        g_node2comp[node] = c;
        atomicAdd(&g_cnt[c], 1.0f);
    }
}

// ---------------------------------------------------------------------------
// h = x @ lin1_w^T (fp32, unchanged)
__global__ void __launch_bounds__(256) k_h(const float* __restrict__ x,
                                           const float* __restrict__ lin1_w,
                                           int N) {
    extern __shared__ float smf[];
    float* wT = smf;
    float* xs = smf + 128 * 129;
    int tid = threadIdx.x;

    for (int idx = tid; idx < 128 * 128; idx += 256) {
        int f = idx >> 7, k = idx & 127;
        wT[k * 129 + f] = lin1_w[idx];
    }
    int n0 = blockIdx.x * 64;
    for (int idx = tid; idx < 64 * 128; idx += 256) {
        int n = idx >> 7, k = idx & 127;
        int gn = n0 + n;
        xs[idx] = (gn < N) ? x[(size_t)gn * HF + k] : 0.0f;
    }
    __syncthreads();

    int f = tid & 127;
    int no = tid >> 7;
#pragma unroll
    for (int grp = 0; grp < 8; ++grp) {
        int e0 = no + 2 * (grp * 4);
        float a0 = 0.f, a1 = 0.f, a2 = 0.f, a3 = 0.f;
#pragma unroll 4
        for (int k4 = 0; k4 < 32; ++k4) {
            float w0 = wT[(4 * k4 + 0) * 129 + f];
            float w1 = wT[(4 * k4 + 1) * 129 + f];
            float w2 = wT[(4 * k4 + 2) * 129 + f];
            float w3 = wT[(4 * k4 + 3) * 129 + f];
            float4 v0 = *(const float4*)&xs[(e0    ) * 128 + 4 * k4];
            float4 v1 = *(const float4*)&xs[(e0 + 2) * 128 + 4 * k4];
            float4 v2 = *(const float4*)&xs[(e0 + 4) * 128 + 4 * k4];
            float4 v3 = *(const float4*)&xs[(e0 + 6) * 128 + 4 * k4];
            a0 = fmaf(v0.x, w0, a0); a0 = fmaf(v0.y, w1, a0);
            a0 = fmaf(v0.z, w2, a0); a0 = fmaf(v0.w, w3, a0);
            a1 = fmaf(v1.x, w0, a1); a1 = fmaf(v1.y, w1, a1);
            a1 = fmaf(v1.z, w2, a1); a1 = fmaf(v1.w, w3, a1);
            a2 = fmaf(v2.x, w0, a2); a2 = fmaf(v2.y, w1, a2);
            a2 = fmaf(v2.z, w2, a2); a2 = fmaf(v2.w, w3, a2);
            a3 = fmaf(v3.x, w0, a3); a3 = fmaf(v3.y, w1, a3);
            a3 = fmaf(v3.z, w2, a3); a3 = fmaf(v3.w, w3, a3);
        }
        int gn = n0 + e0;
        if (gn     < N) g_h[(size_t)(gn    ) * HF + f] = a0;
        if (gn + 2 < N) g_h[(size_t)(gn + 2) * HF + f] = a1;
        if (gn + 4 < N) g_h[(size_t)(gn + 4) * HF + f] = a2;
        if (gn + 6 < N) g_h[(size_t)(gn + 6) * HF + f] = a3;
    }
}

// ---------------------------------------------------------------------------
__global__ void __launch_bounds__(NTHR, 1) k_edge(
    const int* __restrict__ ei, const float* __restrict__ ew,
    const float* __restrict__ attr,
    const float* __restrict__ w1, const float* __restrict__ b1,
    const float* __restrict__ w2, const float* __restrict__ b2,
    int E) {
    extern __shared__ char sm[];
    float* stg   = (float*)(sm + OFF_STG);
    float* b1s   = (float*)(sm + OFF_B1);
    float* b2s   = (float*)(sm + OFF_B2);
    int*   sSrc  = (int*)  (sm + OFF_SRC);
    int*   sCmp  = (int*)  (sm + OFF_CMP);
    float* sCv   = (float*)(sm + OFF_CV);
    uint32 sbase = (uint32)__cvta_generic_to_shared(sm);

    const int tid = threadIdx.x;
    const int w   = tid >> 5;
    const int l   = tid & 31;
    const int g   = l >> 2;
    const int q   = l & 3;

    // ---- one-time weight staging: [n][k]-major fp16 hi/lo ----
    for (int idx = tid; idx < 128 * 36; idx += NTHR) {       // w1: k padded 50->72
        int n = idx / 36, kp = idx % 36;
        int k = 2 * kp;
        float v0 = (k     < 50) ? w1[n * 50 + k]     : 0.0f;
        float v1 = (k + 1 < 50) ? w1[n * 50 + k + 1] : 0.0f;
        uint32 h, lo;
        split2h(v0, v1, h, lo);
        *(uint32*)(sm + OFF_W1H + n * 144 + kp * 4) = h;
        *(uint32*)(sm + OFF_W1L + n * 144 + kp * 4) = lo;
    }
    for (int idx = tid; idx < 128 * 68; idx += NTHR) {       // w2: k padded 128->136
        int n = idx / 68, kp = idx % 68;
        int k = 2 * kp;
        float v0 = (k < 128) ? w2[n * 128 + k]     : 0.0f;
        float v1 = (k < 128) ? w2[n * 128 + k + 1] : 0.0f;
        uint32 h, lo;
        split2h(v0, v1, h, lo);
        *(uint32*)(sm + OFF_W2H + n * 272 + kp * 4) = h;
        *(uint32*)(sm + OFF_W2L + n * 272 + kp * 4) = lo;
    }
    if (tid < 128) { b1s[tid] = b1[tid]; b2s[tid] = b2[tid]; }

    const int numTiles = (E + TE - 1) / TE;
    int tile = blockIdx.x;
    if (tile >= numTiles) return;

    // ---- prologue prefetch of first tile (buf 0) ----
    {
        int tbase = tile * TE;
        for (int i = tid; i < TE * 25; i += NTHR) {
            int e = i / 25, ch = i - e * 25;
            int ge = tbase + e;
            if (ge < E)
                cpa8(sbase + OFF_STG + e * 208 + ch * 8,
                     attr + (size_t)ge * 50 + ch * 2);
        }
        if (tid < TE) {
            int ge = tbase + tid;
            if (ge < E) {
                cpa4(sbase + OFF_SRC + tid * 4, ei + ge);
                cpa4(sbase + OFF_CMP + tid * 4, ei + E + ge);
                cpa4(sbase + OFF_CV  + tid * 4, ew + ge);
            }
        }
        CP_COMMIT();
    }

    int buf = 0;
    for (; tile < numTiles; tile += gridDim.x) {
        int ntile = tile + gridDim.x;
        CP_WAIT0();
        __syncthreads();   // staged data ready; prev tile's smem reads done

        int ebase = tile * TE;
        // ---- transform metadata in place ----
        if (tid < TE) {
            int ge = ebase + tid;
            int srcv = 0, compv = 0;
            float Cv = 0.0f;
            if (ge < E) {
                srcv = sSrc[buf * 128 + tid];
                compv = g_node2comp[sCmp[buf * 128 + tid]];
                float wv = sCv[buf * 128 + tid];
                Cv = 10.0f / (1e-10f + wv * wv) - 1.0f;
            }
            sSrc[buf * 128 + tid] = srcv;
            sCmp[buf * 128 + tid] = compv;
            sCv [buf * 128 + tid] = Cv;
        }
        // ---- convert attr fp32 -> fp16 (single array, K padded to 64) ----
        {
            const float* sb = stg + buf * (128 * 52);
            for (int i = tid; i < 128 * 32; i += NTHR) {
                int row = i >> 5, kp = i & 31;
                int k = 2 * kp;
                float v0 = 0.f, v1 = 0.f;
                if (ebase + row < E && k < 50) {
                    v0 = sb[row * 52 + k];
                    v1 = (k + 1 < 50) ? sb[row * 52 + k + 1] : 0.0f;
                }
                *(uint32*)(sm + OFF_AH + row * 144 + kp * 4) = packh2(v0, v1);
            }
        }
        // ---- prefetch next tile ----
        if (ntile < numTiles) {
            int tbase = ntile * TE;
            int nb = buf ^ 1;
            for (int i = tid; i < TE * 25; i += NTHR) {
                int e = i / 25, ch = i - e * 25;
                int ge = tbase + e;
                if (ge < E)
                    cpa8(sbase + OFF_STG + nb * (128 * 208) + e * 208 + ch * 8,
                         attr + (size_t)ge * 50 + ch * 2);
            }
            if (tid < TE) {
                int ge = tbase + tid;
                if (ge < E) {
                    cpa4(sbase + OFF_SRC + (nb * 128 + tid) * 4, ei + ge);
                    cpa4(sbase + OFF_CMP + (nb * 128 + tid) * 4, ei + E + ge);
                    cpa4(sbase + OFF_CV  + (nb * 128 + tid) * 4, ew + ge);
                }
            }
        }
        CP_COMMIT();
        __syncthreads();   // ah + meta visible

        // ---- load stage-1 A fragments (fp16, single) ----
        uint32 ahf[4][4];
        {
            uint32 arow = sbase + OFF_AH + (16 * w + (l & 15)) * 144 + ((l >> 4) * 16);
#pragma unroll
            for (int t = 0; t < 4; ++t)
                ldmx4(ahf[t][0], ahf[t][1], ahf[t][2], ahf[t][3], arow + t * 32);
        }

        // per-lane edge metadata
        const int rowe = g + ((q & 1) << 3);
        const int eIdx = 16 * w + rowe;
        const float Cv = sCv[buf * 128 + eIdx];
        const int  srcn = sSrc[buf * 128 + eIdx];
        const int  comp = sCmp[buf * 128 + eIdx];

        // ---- stage-2 accumulators init with bias b2 ----
        float acc2[16][4];
#pragma unroll
        for (int nt = 0; nt < 16; ++nt) {
            float2 bb = *(const float2*)&b2s[8 * nt + 2 * q];
            acc2[nt][0] = bb.x; acc2[nt][1] = bb.y;
            acc2[nt][2] = bb.x; acc2[nt][3] = bb.y;
        }

        // ---- main: per stage-2 k-tile j: hidden cols 16j..16j+15, ssp, MMAs --
        for (int j = 0; j < 8; ++j) {
            float a1[2][4];
#pragma unroll
            for (int p = 0; p < 2; ++p) {
                float2 bb = *(const float2*)&b1s[16 * j + 8 * p + 2 * q];
                a1[p][0] = bb.x; a1[p][1] = bb.y;
                a1[p][2] = bb.x; a1[p][3] = bb.y;
            }
#pragma unroll
            for (int t = 0; t < 4; ++t) {
#pragma unroll
                for (int p = 0; p < 2; ++p) {
                    const char* wb = sm + (16 * j + 8 * p + g) * 144 + (16 * t + 2 * q) * 2;
                    uint32 bh0 = *(const uint32*)(wb + OFF_W1H);
                    uint32 bh1 = *(const uint32*)(wb + OFF_W1H + 16);
                    uint32 bl0 = *(const uint32*)(wb + OFF_W1L);
                    uint32 bl1 = *(const uint32*)(wb + OFF_W1L + 16);
                    mma16816(a1[p][0], a1[p][1], a1[p][2], a1[p][3],
                             ahf[t][0], ahf[t][1], ahf[t][2], ahf[t][3], bh0, bh1);
                    mma16816(a1[p][0], a1[p][1], a1[p][2], a1[p][3],
                             ahf[t][0], ahf[t][1], ahf[t][2], ahf[t][3], bl0, bl1);
                }
            }
            // ssp + round -> stage-2 A fragments for k-tile j (fp16, single)
            uint32 ua[4];
            ua[0] = packh2(sspf_fast(a1[0][0]), sspf_fast(a1[0][1]));
            ua[1] = packh2(sspf_fast(a1[0][2]), sspf_fast(a1[0][3]));
            ua[2] = packh2(sspf_fast(a1[1][0]), sspf_fast(a1[1][1]));
            ua[3] = packh2(sspf_fast(a1[1][2]), sspf_fast(a1[1][3]));

#pragma unroll
            for (int nt = 0; nt < 16; ++nt) {
                const char* wb = sm + (8 * nt + g) * 272 + (16 * j + 2 * q) * 2;
                uint32 bh0 = *(const uint32*)(wb + OFF_W2H);
                uint32 bh1 = *(const uint32*)(wb + OFF_W2H + 16);
                uint32 bl0 = *(const uint32*)(wb + OFF_W2L);
                uint32 bl1 = *(const uint32*)(wb + OFF_W2L + 16);
                mma16816(acc2[nt][0], acc2[nt][1], acc2[nt][2], acc2[nt][3],
                         ua[0], ua[1], ua[2], ua[3], bh0, bh1);
                mma16816(acc2[nt][0], acc2[nt][1], acc2[nt][2], acc2[nt][3],
                         ua[0], ua[1], ua[2], ua[3], bl0, bl1);
            }
        }

        // ---- epilogue: shuffle to row-major float4, scale, gather h, scatter --
        {
            const float4* hrow = (const float4*)&g_h[(size_t)srcn * HF];
            float* crow = &g_comp[comp * HF];
            const bool doit = (Cv != 0.0f);
            const int podd = q & 1;
            const int p4 = (q >> 1) << 2;
#pragma unroll
            for (int nt = 0; nt < 16; ++nt) {
                float d0 = acc2[nt][0], d1 = acc2[nt][1];
                float d2 = acc2[nt][2], d3 = acc2[nt][3];
                ull send;
                if (podd) { asm("mov.b64 %0,{%1,%2};" : "=l"(send) : "f"(d0), "f"(d1)); }
                else      { asm("mov.b64 %0,{%1,%2};" : "=l"(send) : "f"(d2), "f"(d3)); }
                ull rcv = __shfl_xor_sync(0xffffffffu, send, 1);
                float rx, ry;
                asm("mov.b64 {%0,%1},%2;" : "=f"(rx), "=f"(ry) : "l"(rcv));
                float v0, v1, v2, v3;
                if (podd) { v0 = rx; v1 = ry; v2 = d2; v3 = d3; }
                else      { v0 = d0; v1 = d1; v2 = rx; v3 = ry; }
                int col0 = 8 * nt + p4;
                if (doit) {
                    float4 h4 = hrow[col0 >> 2];
                    v0 *= Cv * h4.x; v1 *= Cv * h4.y;
                    v2 *= Cv * h4.z; v3 *= Cv * h4.w;
                    redv2(crow + col0,     v0, v1);
                    redv2(crow + col0 + 2, v2, v3);
                }
            }
        }
        buf ^= 1;
    }
}

// ---------------------------------------------------------------------------
// Tail: mean -> lin2 -> ssp -> lin (unchanged)
__global__ void __launch_bounds__(256) k_final(
    const float* __restrict__ lin2_w, const float* __restrict__ lin2_b,
    const float* __restrict__ lin_w,  const float* __restrict__ lin_b,
    float* __restrict__ out) {
    __shared__ float sin_[16 * 128];
    __shared__ float sy[16 * 128];
    __shared__ float swT[32 * 129];
    int tid = threadIdx.x;
    int c0 = blockIdx.x * 16;

    for (int idx = tid; idx < 2048; idx += 256) {
        int c = idx >> 7;
        float cnt = g_cnt[c0 + c];
        sin_[idx] = g_comp[(c0 + c) * HF + (idx & 127)] / fmaxf(cnt, 1.0f);
    }
    __syncthreads();

    int f  = tid & 127;
    int co = tid >> 7;
    float acc[8];
#pragma unroll
    for (int j = 0; j < 8; ++j) acc[j] = lin2_b[f];
    for (int kb = 0; kb < 4; ++kb) {
        __syncthreads();
        for (int idx = tid; idx < 4096; idx += 256) {
            int f_ = idx >> 5, kk = idx & 31;
            swT[kk * 129 + f_] = lin2_w[f_ * 128 + kb * 32 + kk];
        }
        __syncthreads();
        for (int kk = 0; kk < 32; ++kk) {
            float wv = swT[kk * 129 + f];
#pragma unroll
            for (int j = 0; j < 8; ++j)
                acc[j] = fmaf(sin_[(co + 2 * j) * 128 + kb * 32 + kk], wv, acc[j]);
        }
    }
#pragma unroll
    for (int j = 0; j < 8; ++j)
        sy[(co + 2 * j) * 128 + f] = sspf(acc[j]);

    float acc2[8];
#pragma unroll
    for (int j = 0; j < 8; ++j) acc2[j] = lin_b[f];
    for (int kb = 0; kb < 4; ++kb) {
        __syncthreads();
        for (int idx = tid; idx < 4096; idx += 256) {
            int f_ = idx >> 5, kk = idx & 31;
            swT[kk * 129 + f_] = lin_w[f_ * 128 + kb * 32 + kk];
        }
        __syncthreads();
        for (int kk = 0; kk < 32; ++kk) {
            float wv = swT[kk * 129 + f];
#pragma unroll
            for (int j = 0; j < 8; ++j)
                acc2[j] = fmaf(sy[(co + 2 * j) * 128 + kb * 32 + kk], wv, acc2[j]);
        }
    }
#pragma unroll
    for (int j = 0; j < 8; ++j)
        out[(size_t)(c0 + co + 2 * j) * HF + f] = acc2[j];
}

// ---------------------------------------------------------------------------
extern "C" void kernel_launch(void* const* d_in, const int* in_sizes, int n_in,
                              void* d_out, int out_size) {
    const float* x        = (const float*)d_in[0];
    const int*   ei       = (const int*)  d_in[1];
    const float* ew       = (const float*)d_in[2];
    const float* attr     = (const float*)d_in[3];
    const int*   cmember  = (const int*)  d_in[4];
    const int*   cseg     = (const int*)  d_in[5];
    const float* mlp_w1   = (const float*)d_in[6];
    const float* mlp_b1   = (const float*)d_in[7];
    const float* mlp_w2   = (const float*)d_in[8];
    const float* mlp_b2   = (const float*)d_in[9];
    const float* lin1_w   = (const float*)d_in[10];
    const float* lin2_w   = (const float*)d_in[11];
    const float* lin2_b   = (const float*)d_in[12];
    const float* lin_w    = (const float*)d_in[13];
    const float* lin_b    = (const float*)d_in[14];
    float* out = (float*)d_out;

    int N = in_sizes[0] / HF;
    int E = in_sizes[2];
    int NC = out_size / HF;

    void *p_comp, *p_cnt;
    cudaGetSymbolAddress(&p_comp, g_comp);
    cudaGetSymbolAddress(&p_cnt, g_cnt);
    cudaMemsetAsync(p_comp, 0, (size_t)NC * HF * sizeof(float));
    cudaMemsetAsync(p_cnt, 0, (size_t)NC * sizeof(float));

    int sms = 148;
    int dev = 0;
    cudaGetDevice(&dev);
    cudaDeviceGetAttribute(&sms, cudaDevAttrMultiProcessorCount, dev);

    const int SMEM_H = (128 * 129 + 64 * 128) * 4;
    cudaFuncSetAttribute(k_h, cudaFuncAttributeMaxDynamicSharedMemorySize, SMEM_H);
    cudaFuncSetAttribute(k_edge, cudaFuncAttributeMaxDynamicSharedMemorySize, SMEM_E);

    int numTiles = (E + TE - 1) / TE;
    int grid = sms < numTiles ? sms : numTiles;

    k_prep<<<(N + 255) / 256, 256>>>(cmember, cseg, N);
    k_h<<<(N + 63) / 64, 256, SMEM_H>>>(x, lin1_w, N);
    k_edge<<<grid, NTHR, SMEM_E>>>(ei, ew, attr, mlp_w1, mlp_b1,
                                   mlp_w2, mlp_b2, E);
    k_final<<<NC / 16, 256>>>(lin2_w, lin2_b, lin_w, lin_b, out);
}

// round 6
// speedup vs baseline: 4.7451x; 1.2570x over previous
#include <cuda_runtime.h>
#include <cuda_fp16.h>
#include <math.h>
#include <stdint.h>

// ---------------------------------------------------------------------------
// InteractionBlock v6: fp16x2 HMMA edge MLP, 512 thr / TE=256 (occupancy x2),
// fragment-ordered weights (1 x LDS.128 per MMA pair instead of 4 x LDS.32).
// ---------------------------------------------------------------------------

#define HF   128
#define MAXN 50000
#define MAXC 2048
#define TE   256
#define NTHR 512

__device__ float g_h[MAXN * HF];
__device__ float g_comp[MAXC * HF];
__device__ float g_cnt[MAXC];
__device__ int   g_node2comp[MAXN];

typedef unsigned int uint32;
typedef unsigned long long ull;

// ---- smem byte offsets for k_edge ----
#define OFF_STG 0          // fp32 attr staging [256][52]          53248
#define OFF_AH  53248      // fp16 [256 e][72 k] (stride 144B)     36864
#define OFF_W1F 90112      // frag w1 [16 jp][4 t][32 l][16B]      32768
#define OFF_W2F 122880     // frag w2 [16 nt][8 j][32 l][16B]      65536
#define OFF_B1  188416     // float[128]
#define OFF_B2  188928
#define OFF_SRC 189440     // int  [2][256]
#define OFF_CMP 191488     // int  [2][256]
#define OFF_CV  193536     // float[2][256]
#define SMEM_E  195584

__device__ __forceinline__ float sspf(float x) {
    float ax = fabsf(x);
    return fmaxf(x, 0.0f) + log1pf(__expf(-ax)) - 0.6931471805599453f;
}
__device__ __forceinline__ float sspf_fast(float x) {
    float ax = fabsf(x);
    return fmaxf(x, 0.0f) + __logf(1.0f + __expf(-ax)) - 0.6931471805599453f;
}
__device__ __forceinline__ uint32 packh2(float x0, float x1) {
    __half2 hh = __floats2half2_rn(x0, x1);
    return *reinterpret_cast<uint32*>(&hh);
}
__device__ __forceinline__ void split2h(float x0, float x1, uint32& h, uint32& l) {
    __half2 hh = __floats2half2_rn(x0, x1);
    float2 b = __half22float2(hh);
    __half2 ll = __floats2half2_rn(x0 - b.x, x1 - b.y);
    h = *reinterpret_cast<uint32*>(&hh);
    l = *reinterpret_cast<uint32*>(&ll);
}
__device__ __forceinline__ void ldmx4(uint32& r0, uint32& r1, uint32& r2, uint32& r3,
                                      uint32 saddr) {
    asm volatile("ldmatrix.sync.aligned.m8n8.x4.shared.b16 {%0,%1,%2,%3}, [%4];"
                 : "=r"(r0), "=r"(r1), "=r"(r2), "=r"(r3) : "r"(saddr));
}
__device__ __forceinline__ void mma16816(float& d0, float& d1, float& d2, float& d3,
                                         uint32 a0, uint32 a1, uint32 a2, uint32 a3,
                                         uint32 b0, uint32 b1) {
    asm volatile("mma.sync.aligned.m16n8k16.row.col.f32.f16.f16.f32 "
                 "{%0,%1,%2,%3},{%4,%5,%6,%7},{%8,%9},{%0,%1,%2,%3};"
                 : "+f"(d0), "+f"(d1), "+f"(d2), "+f"(d3)
                 : "r"(a0), "r"(a1), "r"(a2), "r"(a3), "r"(b0), "r"(b1));
}
__device__ __forceinline__ void redv2(float* p, float x, float y) {
    asm volatile("red.global.add.v2.f32 [%0], {%1,%2};"
                 :: "l"((ull)p), "f"(x), "f"(y) : "memory");
}
__device__ __forceinline__ void cpa8(unsigned s, const void* g) {
    asm volatile("cp.async.ca.shared.global [%0], [%1], 8;" :: "r"(s), "l"(g));
}
__device__ __forceinline__ void cpa4(unsigned s, const void* g) {
    asm volatile("cp.async.ca.shared.global [%0], [%1], 4;" :: "r"(s), "l"(g));
}
#define CP_COMMIT() asm volatile("cp.async.commit_group;" ::: "memory")
#define CP_WAIT0()  asm volatile("cp.async.wait_group 0;" ::: "memory")

// ---------------------------------------------------------------------------
__global__ void k_prep(const int* __restrict__ comp_member,
                       const int* __restrict__ comp_seg, int N) {
    int i = blockIdx.x * blockDim.x + threadIdx.x;
    if (i < N) {
        int node = comp_member[i];
        int c = comp_seg[i];
        g_node2comp[node] = c;
        atomicAdd(&g_cnt[c], 1.0f);
    }
}

// ---------------------------------------------------------------------------
// h = x @ lin1_w^T (fp32, unchanged)
__global__ void __launch_bounds__(256) k_h(const float* __restrict__ x,
                                           const float* __restrict__ lin1_w,
                                           int N) {
    extern __shared__ float smf[];
    float* wT = smf;
    float* xs = smf + 128 * 129;
    int tid = threadIdx.x;

    for (int idx = tid; idx < 128 * 128; idx += 256) {
        int f = idx >> 7, k = idx & 127;
        wT[k * 129 + f] = lin1_w[idx];
    }
    int n0 = blockIdx.x * 64;
    for (int idx = tid; idx < 64 * 128; idx += 256) {
        int n = idx >> 7, k = idx & 127;
        int gn = n0 + n;
        xs[idx] = (gn < N) ? x[(size_t)gn * HF + k] : 0.0f;
    }
    __syncthreads();

    int f = tid & 127;
    int no = tid >> 7;
#pragma unroll
    for (int grp = 0; grp < 8; ++grp) {
        int e0 = no + 2 * (grp * 4);
        float a0 = 0.f, a1 = 0.f, a2 = 0.f, a3 = 0.f;
#pragma unroll 4
        for (int k4 = 0; k4 < 32; ++k4) {
            float w0 = wT[(4 * k4 + 0) * 129 + f];
            float w1 = wT[(4 * k4 + 1) * 129 + f];
            float w2 = wT[(4 * k4 + 2) * 129 + f];
            float w3 = wT[(4 * k4 + 3) * 129 + f];
            float4 v0 = *(const float4*)&xs[(e0    ) * 128 + 4 * k4];
            float4 v1 = *(const float4*)&xs[(e0 + 2) * 128 + 4 * k4];
            float4 v2 = *(const float4*)&xs[(e0 + 4) * 128 + 4 * k4];
            float4 v3 = *(const float4*)&xs[(e0 + 6) * 128 + 4 * k4];
            a0 = fmaf(v0.x, w0, a0); a0 = fmaf(v0.y, w1, a0);
            a0 = fmaf(v0.z, w2, a0); a0 = fmaf(v0.w, w3, a0);
            a1 = fmaf(v1.x, w0, a1); a1 = fmaf(v1.y, w1, a1);
            a1 = fmaf(v1.z, w2, a1); a1 = fmaf(v1.w, w3, a1);
            a2 = fmaf(v2.x, w0, a2); a2 = fmaf(v2.y, w1, a2);
            a2 = fmaf(v2.z, w2, a2); a2 = fmaf(v2.w, w3, a2);
            a3 = fmaf(v3.x, w0, a3); a3 = fmaf(v3.y, w1, a3);
            a3 = fmaf(v3.z, w2, a3); a3 = fmaf(v3.w, w3, a3);
        }
        int gn = n0 + e0;
        if (gn     < N) g_h[(size_t)(gn    ) * HF + f] = a0;
        if (gn + 2 < N) g_h[(size_t)(gn + 2) * HF + f] = a1;
        if (gn + 4 < N) g_h[(size_t)(gn + 4) * HF + f] = a2;
        if (gn + 6 < N) g_h[(size_t)(gn + 6) * HF + f] = a3;
    }
}

// ---------------------------------------------------------------------------
__global__ void __launch_bounds__(NTHR, 1) k_edge(
    const int* __restrict__ ei, const float* __restrict__ ew,
    const float* __restrict__ attr,
    const float* __restrict__ w1, const float* __restrict__ b1,
    const float* __restrict__ w2, const float* __restrict__ b2,
    int E) {
    extern __shared__ char sm[];
    float* stg   = (float*)(sm + OFF_STG);
    float* b1s   = (float*)(sm + OFF_B1);
    float* b2s   = (float*)(sm + OFF_B2);
    int*   sSrc  = (int*)  (sm + OFF_SRC);
    int*   sCmp  = (int*)  (sm + OFF_CMP);
    float* sCv   = (float*)(sm + OFF_CV);
    uint32 sbase = (uint32)__cvta_generic_to_shared(sm);

    const int tid = threadIdx.x;
    const int w   = tid >> 5;
    const int l   = tid & 31;
    const int g   = l >> 2;
    const int q   = l & 3;

    // ---- one-time weight staging in FRAGMENT order ----
    // W1F entry idx = jp*128 + t*32 + lane : {bh0,bh1,bl0,bl1} 16B
    for (int idx = tid; idx < 2048; idx += NTHR) {
        int lane = idx & 31, t = (idx >> 5) & 3, jp = idx >> 7;
        int gg = lane >> 2, qq = lane & 3;
        int n = 8 * jp + gg;
        int k0 = 16 * t + 2 * qq;
        int k1 = k0 + 8;
        float v00 = (k0     < 50) ? w1[n * 50 + k0]     : 0.0f;
        float v01 = (k0 + 1 < 50) ? w1[n * 50 + k0 + 1] : 0.0f;
        float v10 = (k1     < 50) ? w1[n * 50 + k1]     : 0.0f;
        float v11 = (k1 + 1 < 50) ? w1[n * 50 + k1 + 1] : 0.0f;
        uint32 h0, l0, h1, l1;
        split2h(v00, v01, h0, l0);
        split2h(v10, v11, h1, l1);
        uint4 f;
        f.x = h0; f.y = h1; f.z = l0; f.w = l1;
        *(uint4*)(sm + OFF_W1F + idx * 16) = f;
    }
    // W2F entry idx = nt*256 + j*32 + lane
    for (int idx = tid; idx < 4096; idx += NTHR) {
        int lane = idx & 31, j = (idx >> 5) & 7, nt = idx >> 8;
        int gg = lane >> 2, qq = lane & 3;
        int n = 8 * nt + gg;
        int k0 = 16 * j + 2 * qq;
        int k1 = k0 + 8;
        uint32 h0, l0, h1, l1;
        split2h(w2[n * 128 + k0], w2[n * 128 + k0 + 1], h0, l0);
        split2h(w2[n * 128 + k1], w2[n * 128 + k1 + 1], h1, l1);
        uint4 f;
        f.x = h0; f.y = h1; f.z = l0; f.w = l1;
        *(uint4*)(sm + OFF_W2F + idx * 16) = f;
    }
    if (tid < 128) { b1s[tid] = b1[tid]; b2s[tid] = b2[tid]; }

    const int numTiles = (E + TE - 1) / TE;
    int tile = blockIdx.x;
    if (tile >= numTiles) return;

    // ---- prologue prefetch of first tile (meta buf 0) ----
    {
        int tbase = tile * TE;
        for (int i = tid; i < TE * 25; i += NTHR) {
            int e = i / 25, ch = i - e * 25;
            int ge = tbase + e;
            if (ge < E)
                cpa8(sbase + OFF_STG + e * 208 + ch * 8,
                     attr + (size_t)ge * 50 + ch * 2);
        }
        if (tid < TE) {
            int ge = tbase + tid;
            if (ge < E) {
                cpa4(sbase + OFF_SRC + tid * 4, ei + ge);
                cpa4(sbase + OFF_CMP + tid * 4, ei + E + ge);
                cpa4(sbase + OFF_CV  + tid * 4, ew + ge);
            }
        }
        CP_COMMIT();
    }

    int buf = 0;
    for (; tile < numTiles; tile += gridDim.x) {
        int ntile = tile + gridDim.x;
        int nb = buf ^ 1;
        CP_WAIT0();
        __syncthreads();   // staging + meta[buf] raw ready

        int ebase = tile * TE;
        // ---- transform metadata in place (buf) ----
        if (tid < TE) {
            int ge = ebase + tid;
            int srcv = 0, compv = 0;
            float Cv = 0.0f;
            if (ge < E) {
                srcv = sSrc[buf * TE + tid];
                compv = g_node2comp[sCmp[buf * TE + tid]];
                float wv = sCv[buf * TE + tid];
                Cv = 10.0f / (1e-10f + wv * wv) - 1.0f;
            }
            sSrc[buf * TE + tid] = srcv;
            sCmp[buf * TE + tid] = compv;
            sCv [buf * TE + tid] = Cv;
        }
        // ---- convert attr fp32 -> fp16 into AH (single buffer) ----
        for (int i = tid; i < TE * 32; i += NTHR) {
            int row = i >> 5, kp = i & 31;
            int k = 2 * kp;
            float v0 = 0.f, v1 = 0.f;
            if (ebase + row < E && k < 50) {
                v0 = stg[row * 52 + k];
                v1 = (k + 1 < 50) ? stg[row * 52 + k + 1] : 0.0f;
            }
            *(uint32*)(sm + OFF_AH + row * 144 + kp * 4) = packh2(v0, v1);
        }
        __syncthreads();   // AH + meta ready; staging reads done

        // ---- load stage-1 A fragments ----
        uint32 ahf[4][4];
        {
            uint32 arow = sbase + OFF_AH + (16 * w + (l & 15)) * 144 + ((l >> 4) * 16);
#pragma unroll
            for (int t = 0; t < 4; ++t)
                ldmx4(ahf[t][0], ahf[t][1], ahf[t][2], ahf[t][3], arow + t * 32);
        }
        // per-lane edge metadata
        const int rowe = g + ((q & 1) << 3);
        const int eIdx = 16 * w + rowe;
        const float Cv = sCv[buf * TE + eIdx];
        const int  srcn = sSrc[buf * TE + eIdx];
        const int  comp = sCmp[buf * TE + eIdx];
        __syncthreads();   // AH consumed -> safe for next iteration's convert

        // ---- prefetch next tile (staging now free) ----
        if (ntile < numTiles) {
            int tbase = ntile * TE;
            for (int i = tid; i < TE * 25; i += NTHR) {
                int e = i / 25, ch = i - e * 25;
                int ge = tbase + e;
                if (ge < E)
                    cpa8(sbase + OFF_STG + e * 208 + ch * 8,
                         attr + (size_t)ge * 50 + ch * 2);
            }
            if (tid < TE) {
                int ge = tbase + tid;
                if (ge < E) {
                    cpa4(sbase + OFF_SRC + (nb * TE + tid) * 4, ei + ge);
                    cpa4(sbase + OFF_CMP + (nb * TE + tid) * 4, ei + E + ge);
                    cpa4(sbase + OFF_CV  + (nb * TE + tid) * 4, ew + ge);
                }
            }
        }
        CP_COMMIT();

        // ---- stage-2 accumulators init with bias b2 ----
        float acc2[16][4];
#pragma unroll
        for (int nt = 0; nt < 16; ++nt) {
            float2 bb = *(const float2*)&b2s[8 * nt + 2 * q];
            acc2[nt][0] = bb.x; acc2[nt][1] = bb.y;
            acc2[nt][2] = bb.x; acc2[nt][3] = bb.y;
        }

        // ---- main loop over stage-2 k-tiles ----
        for (int j = 0; j < 8; ++j) {
            float a1[2][4];
#pragma unroll
            for (int p = 0; p < 2; ++p) {
                float2 bb = *(const float2*)&b1s[16 * j + 8 * p + 2 * q];
                a1[p][0] = bb.x; a1[p][1] = bb.y;
                a1[p][2] = bb.x; a1[p][3] = bb.y;
            }
#pragma unroll
            for (int t = 0; t < 4; ++t) {
#pragma unroll
                for (int p = 0; p < 2; ++p) {
                    uint4 f = *(const uint4*)(sm + OFF_W1F
                              + ((2 * j + p) * 4 + t) * 512 + l * 16);
                    mma16816(a1[p][0], a1[p][1], a1[p][2], a1[p][3],
                             ahf[t][0], ahf[t][1], ahf[t][2], ahf[t][3], f.x, f.y);
                    mma16816(a1[p][0], a1[p][1], a1[p][2], a1[p][3],
                             ahf[t][0], ahf[t][1], ahf[t][2], ahf[t][3], f.z, f.w);
                }
            }
            uint32 ua[4];
            ua[0] = packh2(sspf_fast(a1[0][0]), sspf_fast(a1[0][1]));
            ua[1] = packh2(sspf_fast(a1[0][2]), sspf_fast(a1[0][3]));
            ua[2] = packh2(sspf_fast(a1[1][0]), sspf_fast(a1[1][1]));
            ua[3] = packh2(sspf_fast(a1[1][2]), sspf_fast(a1[1][3]));

#pragma unroll
            for (int nt = 0; nt < 16; ++nt) {
                uint4 f = *(const uint4*)(sm + OFF_W2F + (nt * 8 + j) * 512 + l * 16);
                mma16816(acc2[nt][0], acc2[nt][1], acc2[nt][2], acc2[nt][3],
                         ua[0], ua[1], ua[2], ua[3], f.x, f.y);
                mma16816(acc2[nt][0], acc2[nt][1], acc2[nt][2], acc2[nt][3],
                         ua[0], ua[1], ua[2], ua[3], f.z, f.w);
            }
        }

        // ---- epilogue: shuffle pair, scale, gather h[src], scatter ----
        {
            const float4* hrow = (const float4*)&g_h[(size_t)srcn * HF];
            float* crow = &g_comp[comp * HF];
            const bool doit = (Cv != 0.0f);
            const int podd = q & 1;
            const int p4 = (q >> 1) << 2;
#pragma unroll
            for (int nt = 0; nt < 16; ++nt) {
                float d0 = acc2[nt][0], d1 = acc2[nt][1];
                float d2 = acc2[nt][2], d3 = acc2[nt][3];
                ull send;
                if (podd) { asm("mov.b64 %0,{%1,%2};" : "=l"(send) : "f"(d0), "f"(d1)); }
                else      { asm("mov.b64 %0,{%1,%2};" : "=l"(send) : "f"(d2), "f"(d3)); }
                ull rcv = __shfl_xor_sync(0xffffffffu, send, 1);
                float rx, ry;
                asm("mov.b64 {%0,%1},%2;" : "=f"(rx), "=f"(ry) : "l"(rcv));
                float v0, v1, v2, v3;
                if (podd) { v0 = rx; v1 = ry; v2 = d2; v3 = d3; }
                else      { v0 = d0; v1 = d1; v2 = rx; v3 = ry; }
                int col0 = 8 * nt + p4;
                if (doit) {
                    float4 h4 = hrow[col0 >> 2];
                    v0 *= Cv * h4.x; v1 *= Cv * h4.y;
                    v2 *= Cv * h4.z; v3 *= Cv * h4.w;
                    redv2(crow + col0,     v0, v1);
                    redv2(crow + col0 + 2, v2, v3);
                }
            }
        }
        buf = nb;
    }
}

// ---------------------------------------------------------------------------
// Tail: mean -> lin2 -> ssp -> lin (unchanged)
__global__ void __launch_bounds__(256) k_final(
    const float* __restrict__ lin2_w, const float* __restrict__ lin2_b,
    const float* __restrict__ lin_w,  const float* __restrict__ lin_b,
    float* __restrict__ out) {
    __shared__ float sin_[16 * 128];
    __shared__ float sy[16 * 128];
    __shared__ float swT[32 * 129];
    int tid = threadIdx.x;
    int c0 = blockIdx.x * 16;

    for (int idx = tid; idx < 2048; idx += 256) {
        int c = idx >> 7;
        float cnt = g_cnt[c0 + c];
        sin_[idx] = g_comp[(c0 + c) * HF + (idx & 127)] / fmaxf(cnt, 1.0f);
    }
    __syncthreads();

    int f  = tid & 127;
    int co = tid >> 7;
    float acc[8];
#pragma unroll
    for (int j = 0; j < 8; ++j) acc[j] = lin2_b[f];
    for (int kb = 0; kb < 4; ++kb) {
        __syncthreads();
        for (int idx = tid; idx < 4096; idx += 256) {
            int f_ = idx >> 5, kk = idx & 31;
            swT[kk * 129 + f_] = lin2_w[f_ * 128 + kb * 32 + kk];
        }
        __syncthreads();
        for (int kk = 0; kk < 32; ++kk) {
            float wv = swT[kk * 129 + f];
#pragma unroll
            for (int j = 0; j < 8; ++j)
                acc[j] = fmaf(sin_[(co + 2 * j) * 128 + kb * 32 + kk], wv, acc[j]);
        }
    }
#pragma unroll
    for (int j = 0; j < 8; ++j)
        sy[(co + 2 * j) * 128 + f] = sspf(acc[j]);

    float acc2[8];
#pragma unroll
    for (int j = 0; j < 8; ++j) acc2[j] = lin_b[f];
    for (int kb = 0; kb < 4; ++kb) {
        __syncthreads();
        for (int idx = tid; idx < 4096; idx += 256) {
            int f_ = idx >> 5, kk = idx & 31;
            swT[kk * 129 + f_] = lin_w[f_ * 128 + kb * 32 + kk];
        }
        __syncthreads();
        for (int kk = 0; kk < 32; ++kk) {
            float wv = swT[kk * 129 + f];
#pragma unroll
            for (int j = 0; j < 8; ++j)
                acc2[j] = fmaf(sy[(co + 2 * j) * 128 + kb * 32 + kk], wv, acc2[j]);
        }
    }
#pragma unroll
    for (int j = 0; j < 8; ++j)
        out[(size_t)(c0 + co + 2 * j) * HF + f] = acc2[j];
}

// ---------------------------------------------------------------------------
extern "C" void kernel_launch(void* const* d_in, const int* in_sizes, int n_in,
                              void* d_out, int out_size) {
    const float* x        = (const float*)d_in[0];
    const int*   ei       = (const int*)  d_in[1];
    const float* ew       = (const float*)d_in[2];
    const float* attr     = (const float*)d_in[3];
    const int*   cmember  = (const int*)  d_in[4];
    const int*   cseg     = (const int*)  d_in[5];
    const float* mlp_w1   = (const float*)d_in[6];
    const float* mlp_b1   = (const float*)d_in[7];
    const float* mlp_w2   = (const float*)d_in[8];
    const float* mlp_b2   = (const float*)d_in[9];
    const float* lin1_w   = (const float*)d_in[10];
    const float* lin2_w   = (const float*)d_in[11];
    const float* lin2_b   = (const float*)d_in[12];
    const float* lin_w    = (const float*)d_in[13];
    const float* lin_b    = (const float*)d_in[14];
    float* out = (float*)d_out;

    int N = in_sizes[0] / HF;
    int E = in_sizes[2];
    int NC = out_size / HF;

    void *p_comp, *p_cnt;
    cudaGetSymbolAddress(&p_comp, g_comp);
    cudaGetSymbolAddress(&p_cnt, g_cnt);
    cudaMemsetAsync(p_comp, 0, (size_t)NC * HF * sizeof(float));
    cudaMemsetAsync(p_cnt, 0, (size_t)NC * sizeof(float));

    int sms = 148;
    int dev = 0;
    cudaGetDevice(&dev);
    cudaDeviceGetAttribute(&sms, cudaDevAttrMultiProcessorCount, dev);

    const int SMEM_H = (128 * 129 + 64 * 128) * 4;
    cudaFuncSetAttribute(k_h, cudaFuncAttributeMaxDynamicSharedMemorySize, SMEM_H);
    cudaFuncSetAttribute(k_edge, cudaFuncAttributeMaxDynamicSharedMemorySize, SMEM_E);

    int numTiles = (E + TE - 1) / TE;
    int grid = sms < numTiles ? sms : numTiles;

    k_prep<<<(N + 255) / 256, 256>>>(cmember, cseg, N);
    k_h<<<(N + 63) / 64, 256, SMEM_H>>>(x, lin1_w, N);
    k_edge<<<grid, NTHR, SMEM_E>>>(ei, ew, attr, mlp_w1, mlp_b1,
                                   mlp_w2, mlp_b2, E);
    k_final<<<NC / 16, 256>>>(lin2_w, lin2_b, lin_w, lin_b, out);
}

// round 8
// speedup vs baseline: 5.2087x; 1.0977x over previous
#include <cuda_runtime.h>
#include <cuda_fp16.h>
#include <math.h>
#include <stdint.h>

// ---------------------------------------------------------------------------
// InteractionBlock v7 (resubmit; R7 failed on device-busy infra error):
// fp16x1 HMMA edge MLP (weights rounded, single product).
// 512 thr / TE=256, fragment-ordered weights (LDS.64 per MMA).
// ---------------------------------------------------------------------------

#define HF   128
#define MAXN 50000
#define MAXC 2048
#define TE   256
#define NTHR 512

__device__ float g_h[MAXN * HF];
__device__ float g_comp[MAXC * HF];
__device__ float g_cnt[MAXC];
__device__ int   g_node2comp[MAXN];

typedef unsigned int uint32;
typedef unsigned long long ull;

// ---- smem byte offsets for k_edge ----
#define OFF_STG 0          // fp32 attr staging [256][52]          53248
#define OFF_AH  53248      // fp16 [256 e][72 k] (stride 144B)     36864
#define OFF_W1F 90112      // frag w1 [16 jp][4 t][32 l][8B]       16384
#define OFF_W2F 106496     // frag w2 [16 nt][8 j][32 l][8B]       32768
#define OFF_B1  139264     // float[128]
#define OFF_B2  139776
#define OFF_SRC 140288     // int  [2][256]
#define OFF_CMP 142336     // int  [2][256]
#define OFF_CV  144384     // float[2][256]
#define SMEM_E  146432

__device__ __forceinline__ float sspf(float x) {
    float ax = fabsf(x);
    return fmaxf(x, 0.0f) + log1pf(__expf(-ax)) - 0.6931471805599453f;
}
__device__ __forceinline__ float sspf_fast(float x) {
    float ax = fabsf(x);
    return fmaxf(x, 0.0f) + __logf(1.0f + __expf(-ax)) - 0.6931471805599453f;
}
__device__ __forceinline__ uint32 packh2(float x0, float x1) {
    __half2 hh = __floats2half2_rn(x0, x1);
    return *reinterpret_cast<uint32*>(&hh);
}
__device__ __forceinline__ void ldmx4(uint32& r0, uint32& r1, uint32& r2, uint32& r3,
                                      uint32 saddr) {
    asm volatile("ldmatrix.sync.aligned.m8n8.x4.shared.b16 {%0,%1,%2,%3}, [%4];"
                 : "=r"(r0), "=r"(r1), "=r"(r2), "=r"(r3) : "r"(saddr));
}
__device__ __forceinline__ void mma16816(float& d0, float& d1, float& d2, float& d3,
                                         uint32 a0, uint32 a1, uint32 a2, uint32 a3,
                                         uint32 b0, uint32 b1) {
    asm volatile("mma.sync.aligned.m16n8k16.row.col.f32.f16.f16.f32 "
                 "{%0,%1,%2,%3},{%4,%5,%6,%7},{%8,%9},{%0,%1,%2,%3};"
                 : "+f"(d0), "+f"(d1), "+f"(d2), "+f"(d3)
                 : "r"(a0), "r"(a1), "r"(a2), "r"(a3), "r"(b0), "r"(b1));
}
__device__ __forceinline__ void redv2(float* p, float x, float y) {
    asm volatile("red.global.add.v2.f32 [%0], {%1,%2};"
                 :: "l"((ull)p), "f"(x), "f"(y) : "memory");
}
__device__ __forceinline__ void cpa8(unsigned s, const void* g) {
    asm volatile("cp.async.ca.shared.global [%0], [%1], 8;" :: "r"(s), "l"(g));
}
__device__ __forceinline__ void cpa4(unsigned s, const void* g) {
    asm volatile("cp.async.ca.shared.global [%0], [%1], 4;" :: "r"(s), "l"(g));
}
#define CP_COMMIT() asm volatile("cp.async.commit_group;" ::: "memory")
#define CP_WAIT0()  asm volatile("cp.async.wait_group 0;" ::: "memory")

// ---------------------------------------------------------------------------
__global__ void k_prep(const int* __restrict__ comp_member,
                       const int* __restrict__ comp_seg, int N) {
    int i = blockIdx.x * blockDim.x + threadIdx.x;
    if (i < N) {
        int node = comp_member[i];
        int c = comp_seg[i];
        g_node2comp[node] = c;
        atomicAdd(&g_cnt[c], 1.0f);
    }
}

// ---------------------------------------------------------------------------
// h = x @ lin1_w^T (fp32, unchanged)
__global__ void __launch_bounds__(256) k_h(const float* __restrict__ x,
                                           const float* __restrict__ lin1_w,
                                           int N) {
    extern __shared__ float smf[];
    float* wT = smf;
    float* xs = smf + 128 * 129;
    int tid = threadIdx.x;

    for (int idx = tid; idx < 128 * 128; idx += 256) {
        int f = idx >> 7, k = idx & 127;
        wT[k * 129 + f] = lin1_w[idx];
    }
    int n0 = blockIdx.x * 64;
    for (int idx = tid; idx < 64 * 128; idx += 256) {
        int n = idx >> 7, k = idx & 127;
        int gn = n0 + n;
        xs[idx] = (gn < N) ? x[(size_t)gn * HF + k] : 0.0f;
    }
    __syncthreads();

    int f = tid & 127;
    int no = tid >> 7;
#pragma unroll
    for (int grp = 0; grp < 8; ++grp) {
        int e0 = no + 2 * (grp * 4);
        float a0 = 0.f, a1 = 0.f, a2 = 0.f, a3 = 0.f;
#pragma unroll 4
        for (int k4 = 0; k4 < 32; ++k4) {
            float w0 = wT[(4 * k4 + 0) * 129 + f];
            float w1 = wT[(4 * k4 + 1) * 129 + f];
            float w2 = wT[(4 * k4 + 2) * 129 + f];
            float w3 = wT[(4 * k4 + 3) * 129 + f];
            float4 v0 = *(const float4*)&xs[(e0    ) * 128 + 4 * k4];
            float4 v1 = *(const float4*)&xs[(e0 + 2) * 128 + 4 * k4];
            float4 v2 = *(const float4*)&xs[(e0 + 4) * 128 + 4 * k4];
            float4 v3 = *(const float4*)&xs[(e0 + 6) * 128 + 4 * k4];
            a0 = fmaf(v0.x, w0, a0); a0 = fmaf(v0.y, w1, a0);
            a0 = fmaf(v0.z, w2, a0); a0 = fmaf(v0.w, w3, a0);
            a1 = fmaf(v1.x, w0, a1); a1 = fmaf(v1.y, w1, a1);
            a1 = fmaf(v1.z, w2, a1); a1 = fmaf(v1.w, w3, a1);
            a2 = fmaf(v2.x, w0, a2); a2 = fmaf(v2.y, w1, a2);
            a2 = fmaf(v2.z, w2, a2); a2 = fmaf(v2.w, w3, a2);
            a3 = fmaf(v3.x, w0, a3); a3 = fmaf(v3.y, w1, a3);
            a3 = fmaf(v3.z, w2, a3); a3 = fmaf(v3.w, w3, a3);
        }
        int gn = n0 + e0;
        if (gn     < N) g_h[(size_t)(gn    ) * HF + f] = a0;
        if (gn + 2 < N) g_h[(size_t)(gn + 2) * HF + f] = a1;
        if (gn + 4 < N) g_h[(size_t)(gn + 4) * HF + f] = a2;
        if (gn + 6 < N) g_h[(size_t)(gn + 6) * HF + f] = a3;
    }
}

// ---------------------------------------------------------------------------
__global__ void __launch_bounds__(NTHR, 1) k_edge(
    const int* __restrict__ ei, const float* __restrict__ ew,
    const float* __restrict__ attr,
    const float* __restrict__ w1, const float* __restrict__ b1,
    const float* __restrict__ w2, const float* __restrict__ b2,
    int E) {
    extern __shared__ char sm[];
    float* stg   = (float*)(sm + OFF_STG);
    float* b1s   = (float*)(sm + OFF_B1);
    float* b2s   = (float*)(sm + OFF_B2);
    int*   sSrc  = (int*)  (sm + OFF_SRC);
    int*   sCmp  = (int*)  (sm + OFF_CMP);
    float* sCv   = (float*)(sm + OFF_CV);
    uint32 sbase = (uint32)__cvta_generic_to_shared(sm);

    const int tid = threadIdx.x;
    const int w   = tid >> 5;
    const int l   = tid & 31;
    const int g   = l >> 2;
    const int q   = l & 3;

    // ---- one-time weight staging in FRAGMENT order (hi only, 8B/entry) ----
    // W1F entry idx = jp*128 + t*32 + lane : {bh0,bh1}
    for (int idx = tid; idx < 2048; idx += NTHR) {
        int lane = idx & 31, t = (idx >> 5) & 3, jp = idx >> 7;
        int gg = lane >> 2, qq = lane & 3;
        int n = 8 * jp + gg;
        int k0 = 16 * t + 2 * qq;
        int k1 = k0 + 8;
        float v00 = (k0     < 50) ? w1[n * 50 + k0]     : 0.0f;
        float v01 = (k0 + 1 < 50) ? w1[n * 50 + k0 + 1] : 0.0f;
        float v10 = (k1     < 50) ? w1[n * 50 + k1]     : 0.0f;
        float v11 = (k1 + 1 < 50) ? w1[n * 50 + k1 + 1] : 0.0f;
        uint2 f;
        f.x = packh2(v00, v01);
        f.y = packh2(v10, v11);
        *(uint2*)(sm + OFF_W1F + idx * 8) = f;
    }
    // W2F entry idx = nt*256 + j*32 + lane
    for (int idx = tid; idx < 4096; idx += NTHR) {
        int lane = idx & 31, j = (idx >> 5) & 7, nt = idx >> 8;
        int gg = lane >> 2, qq = lane & 3;
        int n = 8 * nt + gg;
        int k0 = 16 * j + 2 * qq;
        int k1 = k0 + 8;
        uint2 f;
        f.x = packh2(w2[n * 128 + k0], w2[n * 128 + k0 + 1]);
        f.y = packh2(w2[n * 128 + k1], w2[n * 128 + k1 + 1]);
        *(uint2*)(sm + OFF_W2F + idx * 8) = f;
    }
    if (tid < 128) { b1s[tid] = b1[tid]; b2s[tid] = b2[tid]; }

    const int numTiles = (E + TE - 1) / TE;
    int tile = blockIdx.x;
    if (tile >= numTiles) return;

    // ---- prologue prefetch of first tile (meta buf 0) ----
    {
        int tbase = tile * TE;
        for (int i = tid; i < TE * 25; i += NTHR) {
            int e = i / 25, ch = i - e * 25;
            int ge = tbase + e;
            if (ge < E)
                cpa8(sbase + OFF_STG + e * 208 + ch * 8,
                     attr + (size_t)ge * 50 + ch * 2);
        }
        if (tid < TE) {
            int ge = tbase + tid;
            if (ge < E) {
                cpa4(sbase + OFF_SRC + tid * 4, ei + ge);
                cpa4(sbase + OFF_CMP + tid * 4, ei + E + ge);
                cpa4(sbase + OFF_CV  + tid * 4, ew + ge);
            }
        }
        CP_COMMIT();
    }

    int buf = 0;
    for (; tile < numTiles; tile += gridDim.x) {
        int ntile = tile + gridDim.x;
        int nb = buf ^ 1;
        CP_WAIT0();
        __syncthreads();   // staging + meta[buf] raw ready

        int ebase = tile * TE;
        // ---- transform metadata in place (buf) ----
        if (tid < TE) {
            int ge = ebase + tid;
            int srcv = 0, compv = 0;
            float Cv = 0.0f;
            if (ge < E) {
                srcv = sSrc[buf * TE + tid];
                compv = g_node2comp[sCmp[buf * TE + tid]];
                float wv = sCv[buf * TE + tid];
                Cv = 10.0f / (1e-10f + wv * wv) - 1.0f;
            }
            sSrc[buf * TE + tid] = srcv;
            sCmp[buf * TE + tid] = compv;
            sCv [buf * TE + tid] = Cv;
        }
        // ---- convert attr fp32 -> fp16 into AH (single buffer) ----
        for (int i = tid; i < TE * 32; i += NTHR) {
            int row = i >> 5, kp = i & 31;
            int k = 2 * kp;
            float v0 = 0.f, v1 = 0.f;
            if (ebase + row < E && k < 50) {
                v0 = stg[row * 52 + k];
                v1 = (k + 1 < 50) ? stg[row * 52 + k + 1] : 0.0f;
            }
            *(uint32*)(sm + OFF_AH + row * 144 + kp * 4) = packh2(v0, v1);
        }
        __syncthreads();   // AH + meta ready; staging reads done

        // ---- load stage-1 A fragments ----
        uint32 ahf[4][4];
        {
            uint32 arow = sbase + OFF_AH + (16 * w + (l & 15)) * 144 + ((l >> 4) * 16);
#pragma unroll
            for (int t = 0; t < 4; ++t)
                ldmx4(ahf[t][0], ahf[t][1], ahf[t][2], ahf[t][3], arow + t * 32);
        }
        // per-lane edge metadata
        const int rowe = g + ((q & 1) << 3);
        const int eIdx = 16 * w + rowe;
        const float Cv = sCv[buf * TE + eIdx];
        const int  srcn = sSrc[buf * TE + eIdx];
        const int  comp = sCmp[buf * TE + eIdx];
        __syncthreads();   // AH consumed -> safe for next iteration's convert

        // ---- prefetch next tile (staging now free) ----
        if (ntile < numTiles) {
            int tbase = ntile * TE;
            for (int i = tid; i < TE * 25; i += NTHR) {
                int e = i / 25, ch = i - e * 25;
                int ge = tbase + e;
                if (ge < E)
                    cpa8(sbase + OFF_STG + e * 208 + ch * 8,
                         attr + (size_t)ge * 50 + ch * 2);
            }
            if (tid < TE) {
                int ge = tbase + tid;
                if (ge < E) {
                    cpa4(sbase + OFF_SRC + (nb * TE + tid) * 4, ei + ge);
                    cpa4(sbase + OFF_CMP + (nb * TE + tid) * 4, ei + E + ge);
                    cpa4(sbase + OFF_CV  + (nb * TE + tid) * 4, ew + ge);
                }
            }
        }
        CP_COMMIT();

        // ---- stage-2 accumulators init with bias b2 ----
        float acc2[16][4];
#pragma unroll
        for (int nt = 0; nt < 16; ++nt) {
            float2 bb = *(const float2*)&b2s[8 * nt + 2 * q];
            acc2[nt][0] = bb.x; acc2[nt][1] = bb.y;
            acc2[nt][2] = bb.x; acc2[nt][3] = bb.y;
        }

        // ---- main loop over stage-2 k-tiles ----
        for (int j = 0; j < 8; ++j) {
            float a1[2][4];
#pragma unroll
            for (int p = 0; p < 2; ++p) {
                float2 bb = *(const float2*)&b1s[16 * j + 8 * p + 2 * q];
                a1[p][0] = bb.x; a1[p][1] = bb.y;
                a1[p][2] = bb.x; a1[p][3] = bb.y;
            }
#pragma unroll
            for (int t = 0; t < 4; ++t) {
#pragma unroll
                for (int p = 0; p < 2; ++p) {
                    uint2 f = *(const uint2*)(sm + OFF_W1F
                              + ((2 * j + p) * 4 + t) * 256 + l * 8);
                    mma16816(a1[p][0], a1[p][1], a1[p][2], a1[p][3],
                             ahf[t][0], ahf[t][1], ahf[t][2], ahf[t][3], f.x, f.y);
                }
            }
            uint32 ua[4];
            ua[0] = packh2(sspf_fast(a1[0][0]), sspf_fast(a1[0][1]));
            ua[1] = packh2(sspf_fast(a1[0][2]), sspf_fast(a1[0][3]));
            ua[2] = packh2(sspf_fast(a1[1][0]), sspf_fast(a1[1][1]));
            ua[3] = packh2(sspf_fast(a1[1][2]), sspf_fast(a1[1][3]));

#pragma unroll
            for (int nt = 0; nt < 16; ++nt) {
                uint2 f = *(const uint2*)(sm + OFF_W2F + (nt * 8 + j) * 256 + l * 8);
                mma16816(acc2[nt][0], acc2[nt][1], acc2[nt][2], acc2[nt][3],
                         ua[0], ua[1], ua[2], ua[3], f.x, f.y);
            }
        }

        // ---- epilogue: shuffle pair, scale, gather h[src], scatter ----
        {
            const float4* hrow = (const float4*)&g_h[(size_t)srcn * HF];
            float* crow = &g_comp[comp * HF];
            const bool doit = (Cv != 0.0f);
            const int podd = q & 1;
            const int p4 = (q >> 1) << 2;
#pragma unroll
            for (int nt = 0; nt < 16; ++nt) {
                float d0 = acc2[nt][0], d1 = acc2[nt][1];
                float d2 = acc2[nt][2], d3 = acc2[nt][3];
                ull send;
                if (podd) { asm("mov.b64 %0,{%1,%2};" : "=l"(send) : "f"(d0), "f"(d1)); }
                else      { asm("mov.b64 %0,{%1,%2};" : "=l"(send) : "f"(d2), "f"(d3)); }
                ull rcv = __shfl_xor_sync(0xffffffffu, send, 1);
                float rx, ry;
                asm("mov.b64 {%0,%1},%2;" : "=f"(rx), "=f"(ry) : "l"(rcv));
                float v0, v1, v2, v3;
                if (podd) { v0 = rx; v1 = ry; v2 = d2; v3 = d3; }
                else      { v0 = d0; v1 = d1; v2 = rx; v3 = ry; }
                int col0 = 8 * nt + p4;
                if (doit) {
                    float4 h4 = hrow[col0 >> 2];
                    v0 *= Cv * h4.x; v1 *= Cv * h4.y;
                    v2 *= Cv * h4.z; v3 *= Cv * h4.w;
                    redv2(crow + col0,     v0, v1);
                    redv2(crow + col0 + 2, v2, v3);
                }
            }
        }
        buf = nb;
    }
}

// ---------------------------------------------------------------------------
// Tail: mean -> lin2 -> ssp -> lin (unchanged)
__global__ void __launch_bounds__(256) k_final(
    const float* __restrict__ lin2_w, const float* __restrict__ lin2_b,
    const float* __restrict__ lin_w,  const float* __restrict__ lin_b,
    float* __restrict__ out) {
    __shared__ float sin_[16 * 128];
    __shared__ float sy[16 * 128];
    __shared__ float swT[32 * 129];
    int tid = threadIdx.x;
    int c0 = blockIdx.x * 16;

    for (int idx = tid; idx < 2048; idx += 256) {
        int c = idx >> 7;
        float cnt = g_cnt[c0 + c];
        sin_[idx] = g_comp[(c0 + c) * HF + (idx & 127)] / fmaxf(cnt, 1.0f);
    }
    __syncthreads();

    int f  = tid & 127;
    int co = tid >> 7;
    float acc[8];
#pragma unroll
    for (int j = 0; j < 8; ++j) acc[j] = lin2_b[f];
    for (int kb = 0; kb < 4; ++kb) {
        __syncthreads();
        for (int idx = tid; idx < 4096; idx += 256) {
            int f_ = idx >> 5, kk = idx & 31;
            swT[kk * 129 + f_] = lin2_w[f_ * 128 + kb * 32 + kk];
        }
        __syncthreads();
        for (int kk = 0; kk < 32; ++kk) {
            float wv = swT[kk * 129 + f];
#pragma unroll
            for (int j = 0; j < 8; ++j)
                acc[j] = fmaf(sin_[(co + 2 * j) * 128 + kb * 32 + kk], wv, acc[j]);
        }
    }
#pragma unroll
    for (int j = 0; j < 8; ++j)
        sy[(co + 2 * j) * 128 + f] = sspf(acc[j]);

    float acc2[8];
#pragma unroll
    for (int j = 0; j < 8; ++j) acc2[j] = lin_b[f];
    for (int kb = 0; kb < 4; ++kb) {
        __syncthreads();
        for (int idx = tid; idx < 4096; idx += 256) {
            int f_ = idx >> 5, kk = idx & 31;
            swT[kk * 129 + f_] = lin_w[f_ * 128 + kb * 32 + kk];
        }
        __syncthreads();
        for (int kk = 0; kk < 32; ++kk) {
            float wv = swT[kk * 129 + f];
#pragma unroll
            for (int j = 0; j < 8; ++j)
                acc2[j] = fmaf(sy[(co + 2 * j) * 128 + kb * 32 + kk], wv, acc2[j]);
        }
    }
#pragma unroll
    for (int j = 0; j < 8; ++j)
        out[(size_t)(c0 + co + 2 * j) * HF + f] = acc2[j];
}

// ---------------------------------------------------------------------------
extern "C" void kernel_launch(void* const* d_in, const int* in_sizes, int n_in,
                              void* d_out, int out_size) {
    const float* x        = (const float*)d_in[0];
    const int*   ei       = (const int*)  d_in[1];
    const float* ew       = (const float*)d_in[2];
    const float* attr     = (const float*)d_in[3];
    const int*   cmember  = (const int*)  d_in[4];
    const int*   cseg     = (const int*)  d_in[5];
    const float* mlp_w1   = (const float*)d_in[6];
    const float* mlp_b1   = (const float*)d_in[7];
    const float* mlp_w2   = (const float*)d_in[8];
    const float* mlp_b2   = (const float*)d_in[9];
    const float* lin1_w   = (const float*)d_in[10];
    const float* lin2_w   = (const float*)d_in[11];
    const float* lin2_b   = (const float*)d_in[12];
    const float* lin_w    = (const float*)d_in[13];
    const float* lin_b    = (const float*)d_in[14];
    float* out = (float*)d_out;

    int N = in_sizes[0] / HF;
    int E = in_sizes[2];
    int NC = out_size / HF;

    void *p_comp, *p_cnt;
    cudaGetSymbolAddress(&p_comp, g_comp);
    cudaGetSymbolAddress(&p_cnt, g_cnt);
    cudaMemsetAsync(p_comp, 0, (size_t)NC * HF * sizeof(float));
    cudaMemsetAsync(p_cnt, 0, (size_t)NC * sizeof(float));

    int sms = 148;
    int dev = 0;
    cudaGetDevice(&dev);
    cudaDeviceGetAttribute(&sms, cudaDevAttrMultiProcessorCount, dev);

    const int SMEM_H = (128 * 129 + 64 * 128) * 4;
    cudaFuncSetAttribute(k_h, cudaFuncAttributeMaxDynamicSharedMemorySize, SMEM_H);
    cudaFuncSetAttribute(k_edge, cudaFuncAttributeMaxDynamicSharedMemorySize, SMEM_E);

    int numTiles = (E + TE - 1) / TE;
    int grid = sms < numTiles ? sms : numTiles;

    k_prep<<<(N + 255) / 256, 256>>>(cmember, cseg, N);
    k_h<<<(N + 63) / 64, 256, SMEM_H>>>(x, lin1_w, N);
    k_edge<<<grid, NTHR, SMEM_E>>>(ei, ew, attr, mlp_w1, mlp_b1,
                                   mlp_w2, mlp_b2, E);
    k_final<<<NC / 16, 256>>>(lin2_w, lin2_b, lin_w, lin_b, out);
}